// round 13
// baseline (speedup 1.0000x reference)
#include <cuda_runtime.h>
#include <cuda_bf16.h>
#include <cuda_fp16.h>
#include <cuda_fp8.h>
#include <cstdint>
#include <math.h>

#define BB 8192
#define HH 4096
#define GHH 1024

// ---------------- scratch (device globals; allocation-free rule) ----------------
__device__ uint8_t       g_hidden8[(size_t)BB * HH];
__device__ uint8_t       g_Wsim8[(size_t)HH * HH];
__device__ uint8_t       g_Wval8[(size_t)HH * HH];
__device__ uint8_t       g_Wg18[(size_t)GHH * 2 * HH];
__device__ uint8_t       g_Wg28[(size_t)HH * GHH];
__device__ __nv_bfloat16 g_proj_bf[(size_t)BB * HH];
__device__ uint8_t       g_normed8[(size_t)BB * HH];
__device__ uint8_t       g_values8[(size_t)BB * HH];
__device__ uint8_t       g_valuesT8[(size_t)HH * BB];
__device__ float         g_sim_f32[(size_t)BB * BB];
__device__ uint8_t       g_weights8[(size_t)BB * BB];
__device__ __nv_bfloat16 g_cross_bf[(size_t)BB * HH];
__device__ uint8_t       g_gatein8[(size_t)BB * 2 * HH];
__device__ uint8_t       g_h18[(size_t)BB * GHH];
__device__ unsigned char g_mask_u8[BB];

// scales: hidden x16, W x256, normed x64, weights x16384, values x16, cross(gatein) x16, h1 x64

// ---------------- helpers ----------------
__device__ __forceinline__ uint32_t smem_u32(const void* p) {
    return (uint32_t)__cvta_generic_to_shared(p);
}
__device__ __forceinline__ uint8_t f2e4m3(float v) {
    return (uint8_t)__nv_cvt_float_to_fp8(v, __NV_SATFINITE, __NV_E4M3);
}

// ---------------- fused mask detect + expand (single block) ----------------
__global__ void mask_fused_kernel(const unsigned char* m, unsigned char* out) {
    __shared__ int s_nonbin, s_off4, s_fbad, s_bfbad, s_code;
    if (threadIdx.x == 0) { s_nonbin = 0; s_off4 = 0; s_fbad = 0; s_bfbad = 0; }
    __syncthreads();
    int nonbin = 0, off4 = 0, fbad = 0, bfbad = 0;
    for (int j = threadIdx.x; j < 8192; j += 256) {
        unsigned char b = m[j];
        if (b > 1) nonbin++;
        if ((j & 3) != 0 && b != 0) off4++;
    }
    const uint32_t* u = (const uint32_t*)m;
    for (int i = threadIdx.x; i < 2048; i += 256) {
        uint32_t w = u[i];
        if (!(w == 0u || w == 0x3f800000u)) fbad++;
    }
    const uint16_t* h = (const uint16_t*)m;
    for (int i = threadIdx.x; i < 4096; i += 256) {
        uint16_t x = h[i];
        if (!(x == 0 || x == 0x3f80)) bfbad++;
    }
    atomicAdd(&s_nonbin, nonbin);
    atomicAdd(&s_off4, off4);
    atomicAdd(&s_fbad, fbad);
    atomicAdd(&s_bfbad, bfbad);
    __syncthreads();
    if (threadIdx.x == 0) {
        int code;
        if (s_nonbin == 0) code = (s_off4 > 0) ? 0 : 1;
        else if (s_fbad == 0) code = 2;
        else if (s_bfbad == 0) code = 3;
        else code = 1;
        s_code = code;
    }
    __syncthreads();
    int code = s_code;
    for (int i = threadIdx.x; i < BB; i += 256) {
        bool v;
        if (code == 0)      v = ((const unsigned char*)m)[i] != 0;
        else if (code == 1) v = ((const int*)m)[i] != 0;
        else if (code == 2) v = ((const float*)m)[i] != 0.0f;
        else                v = (((const uint16_t*)m)[i] & 0x7fff) != 0;
        out[i] = v ? 1 : 0;
    }
}

// ---------------- fp32 -> fp8 convert (scale) ----------------
__global__ void f32_to_fp8_kernel(const float* __restrict__ in,
                                  uint8_t* __restrict__ out, float scale, long n4) {
    long i = (long)blockIdx.x * blockDim.x + threadIdx.x;
    if (i < n4) {
        float4 v = ((const float4*)in)[i];
        uint32_t p = (uint32_t)f2e4m3(v.x * scale) |
                     ((uint32_t)f2e4m3(v.y * scale) << 8) |
                     ((uint32_t)f2e4m3(v.z * scale) << 16) |
                     ((uint32_t)f2e4m3(v.w * scale) << 24);
        ((uint32_t*)out)[i] = p;
    }
}

// hidden -> g_hidden8 AND first half of g_gatein8, scale 16
__global__ void hidden_to_fp8_kernel(const float* __restrict__ in,
                                     uint8_t* __restrict__ out,
                                     uint8_t* __restrict__ gatein) {
    long i = ((long)blockIdx.x * blockDim.x + threadIdx.x);
    if (i >= (long)BB * HH / 4) return;
    float4 v = ((const float4*)in)[i];
    uint32_t p = (uint32_t)f2e4m3(v.x * 16.f) |
                 ((uint32_t)f2e4m3(v.y * 16.f) << 8) |
                 ((uint32_t)f2e4m3(v.z * 16.f) << 16) |
                 ((uint32_t)f2e4m3(v.w * 16.f) << 24);
    ((uint32_t*)out)[i] = p;
    long e = i * 4;
    long b = e >> 12;            // /HH
    int  j = (int)(e & (HH - 1));
    *(uint32_t*)(gatein + b * (2 * HH) + j) = p;
}

// ---------------- row L2 normalize: bf16 proj -> fp8 normed (x64) ----------------
__global__ void normalize_rows_kernel(const __nv_bfloat16* __restrict__ p,
                                      uint8_t* __restrict__ normed) {
    int row = blockIdx.x;
    const __nv_bfloat16* r = p + (size_t)row * HH;
    float s = 0.f;
    for (int j = threadIdx.x; j < HH; j += 256) {
        float v = __bfloat162float(r[j]);
        s += v * v;
    }
#pragma unroll
    for (int o = 16; o > 0; o >>= 1) s += __shfl_xor_sync(0xffffffffu, s, o);
    __shared__ float ws[8];
    int w = threadIdx.x >> 5, l = threadIdx.x & 31;
    if (l == 0) ws[w] = s;
    __syncthreads();
    if (threadIdx.x < 32) {
        float x = (threadIdx.x < 8) ? ws[threadIdx.x] : 0.f;
#pragma unroll
        for (int o = 4; o > 0; o >>= 1) x += __shfl_xor_sync(0xffffffffu, x, o);
        if (threadIdx.x == 0) ws[0] = x;
    }
    __syncthreads();
    float scale = 64.f / fmaxf(sqrtf(ws[0]), 1e-12f);
    uint8_t* nr = normed + (size_t)row * HH;
    for (int j = threadIdx.x; j < HH / 4; j += 256) {
        float v0 = __bfloat162float(r[j * 4 + 0]) * scale;
        float v1 = __bfloat162float(r[j * 4 + 1]) * scale;
        float v2 = __bfloat162float(r[j * 4 + 2]) * scale;
        float v3 = __bfloat162float(r[j * 4 + 3]) * scale;
        ((uint32_t*)nr)[j] = (uint32_t)f2e4m3(v0) | ((uint32_t)f2e4m3(v1) << 8) |
                             ((uint32_t)f2e4m3(v2) << 16) | ((uint32_t)f2e4m3(v3) << 24);
    }
}

// ---------------- masked softmax: f32 sim -> fp8 weights (x16384) ----------------
__global__ void softmax_mask_kernel(const float* __restrict__ sim,
                                    const unsigned char* __restrict__ mask,
                                    uint8_t* __restrict__ wts) {
    int row = blockIdx.x;
    __shared__ float sv[BB];
    __shared__ float red[8];
    const float* sr = sim + (size_t)row * BB;
    float mx = -INFINITY;
    for (int j = threadIdx.x; j < BB; j += 256) {
        float v = sr[j];
        if (j == row || mask[j] == 0) v = -INFINITY;
        sv[j] = v;
        mx = fmaxf(mx, v);
    }
#pragma unroll
    for (int o = 16; o > 0; o >>= 1) mx = fmaxf(mx, __shfl_xor_sync(0xffffffffu, mx, o));
    int w = threadIdx.x >> 5, l = threadIdx.x & 31;
    if (l == 0) red[w] = mx;
    __syncthreads();
    if (threadIdx.x < 32) {
        float x = (threadIdx.x < 8) ? red[threadIdx.x] : -INFINITY;
#pragma unroll
        for (int o = 4; o > 0; o >>= 1) x = fmaxf(x, __shfl_xor_sync(0xffffffffu, x, o));
        if (threadIdx.x == 0) red[0] = x;
    }
    __syncthreads();
    float M = red[0];
    __syncthreads();
    float sum = 0.f;
    for (int j = threadIdx.x; j < BB; j += 256) {
        float v = sv[j];
        float e = (v == -INFINITY) ? 0.f : __expf(v - M);
        sv[j] = e;
        sum += e;
    }
#pragma unroll
    for (int o = 16; o > 0; o >>= 1) sum += __shfl_xor_sync(0xffffffffu, sum, o);
    if (l == 0) red[w] = sum;
    __syncthreads();
    if (threadIdx.x < 32) {
        float x = (threadIdx.x < 8) ? red[threadIdx.x] : 0.f;
#pragma unroll
        for (int o = 4; o > 0; o >>= 1) x += __shfl_xor_sync(0xffffffffu, x, o);
        if (threadIdx.x == 0) red[0] = x;
    }
    __syncthreads();
    float S = red[0];
    float inv = (S > 0.f) ? 16384.f / S : 0.f;   // x16384 keeps f16 accumulators safe
    uint8_t* wr = wts + (size_t)row * BB;
    for (int j = threadIdx.x; j < BB / 4; j += 256) {
        ((uint32_t*)wr)[j] = (uint32_t)f2e4m3(sv[j * 4 + 0] * inv) |
                             ((uint32_t)f2e4m3(sv[j * 4 + 1] * inv) << 8) |
                             ((uint32_t)f2e4m3(sv[j * 4 + 2] * inv) << 16) |
                             ((uint32_t)f2e4m3(sv[j * 4 + 3] * inv) << 24);
    }
}

// ---------------- u8 transpose (values -> valuesT) ----------------
__global__ void transpose_u8_kernel(const uint8_t* __restrict__ in,
                                    uint8_t* __restrict__ out, int R, int C) {
    __shared__ uint8_t tile[32][33];
    int x = blockIdx.x * 32 + threadIdx.x;
    int y0 = blockIdx.y * 32 + threadIdx.y;
#pragma unroll
    for (int i = 0; i < 32; i += 8)
        tile[threadIdx.y + i][threadIdx.x] = in[(size_t)(y0 + i) * C + x];
    __syncthreads();
    int x2 = blockIdx.y * 32 + threadIdx.x;
    int y2 = blockIdx.x * 32 + threadIdx.y;
#pragma unroll
    for (int i = 0; i < 32; i += 8)
        out[(size_t)(y2 + i) * R + x2] = tile[threadIdx.x][threadIdx.y + i];
}

// ================= fp8 NT GEMM (mma.sync m16n8k32 e4m3, f16 accum) ==========
// C = A * B^T. CTA tile 128x256, warp tile 64x64 (8 warps 2Mx4N), K-stage 128B,
// XOR-swizzled smem, 2-stage cp.async pipeline (single sync/stage), 2 CTAs/SM.
// ldsm/QMMA = 0.25; int overhead amortized over 32 MMAs per ks-step.
// EPI: 0=f32(desc), 1=bf16(desc), 2=fp8(desc*oscale),
//      3=cross: bf16 + fp8 into gatein second half,
//      4=gelu(desc*acc+bias)->fp8, 5=hid+sigmoid(desc*acc+bias)*cross->f32,
//      6=f32(desc) symmetric: skip tiles fully above diagonal; mirror via
//        two-pass smem-staged transpose (coalesced float4 rows)
#define A_BYTES (128 * 128)                   // 16384
#define B_BYTES (256 * 128)                   // 32768
#define STAGE_BYTES (A_BYTES + B_BYTES)       // 49152
#define GEMM_DYN_SMEM (2 * STAGE_BYTES + 256) // 98560

template <int EPI>
__global__ void __launch_bounds__(256, 2)
gemm_nt_fp8(const uint8_t* __restrict__ A,
            const uint8_t* __restrict__ Bm,
            void* __restrict__ Cv,
            int M, int N, int K,
            float desc, float oscale,
            const float* __restrict__ bias,
            const float* __restrict__ hid,
            const __nv_bfloat16* __restrict__ crossp,
            uint8_t* __restrict__ out2) {
    // symmetric: rows [by*128, +128), cols [bx*256, +256); skip if fully above diag
    if (EPI == 6 && (int)blockIdx.x * 256 >= (int)blockIdx.y * 128 + 128) return;

    extern __shared__ char dynsm[];
    const uint32_t sbase = (smem_u32(dynsm) + 127u) & ~127u;

    const int t = threadIdx.x;
    const int warp = t >> 5, lane = t & 31;
    const int wm = (warp & 1) * 64;        // 2 warps over M
    const int wn = (warp >> 1) * 64;       // 4 warps over N (256)
    const int m0 = blockIdx.y * 128;
    const int n0 = blockIdx.x * 256;
    const int KT = K >> 7;                 // 128-byte K stages

    // ---- producer addressing (XOR swizzle on 16B chunks) ----
    const int frow = t >> 3;
    const int fch = t & 7;
    const uint32_t swch = (uint32_t)(fch ^ (frow & 7)) * 16;
    const uint32_t sAoff = (uint32_t)frow * 128 + swch;
    const uint32_t sBoff = A_BYTES + (uint32_t)frow * 128 + swch;
    const uint8_t* gA = A + (size_t)(m0 + frow) * K + fch * 16;
    const uint8_t* gB = Bm + (size_t)(n0 + frow) * K + fch * 16;

    // ---- consumer addressing ----
    const int crow = lane & 15;
    const int hi = lane >> 4;
    const int rx = crow & 7;
    const uint32_t aRow0 = (uint32_t)(wm + crow) * 128;
    const uint32_t bRow0 = A_BYTES + (uint32_t)(wn + crow) * 128;

    // f16x2 accumulators: acc[i][j][h] = cols (col,col+1) of row (base+h*8)
    uint32_t acc[4][8][2];
#pragma unroll
    for (int i = 0; i < 4; i++)
#pragma unroll
        for (int j = 0; j < 8; j++) { acc[i][j][0] = 0u; acc[i][j][1] = 0u; }

    auto fill = [&](int kt, int st) {
        const uint32_t stb = sbase + st * STAGE_BYTES;
        const size_t kb = (size_t)kt * 128;
#pragma unroll
        for (int i = 0; i < 4; i++) {          // A: 128 rows
            uint32_t dst = stb + sAoff + i * (32 * 128);
            const void* gp = gA + kb + (size_t)i * 32 * K;
            asm volatile("cp.async.cg.shared.global [%0], [%1], 16;\n" ::"r"(dst), "l"(gp));
        }
#pragma unroll
        for (int i = 0; i < 8; i++) {          // B: 256 rows
            uint32_t dst = stb + sBoff + i * (32 * 128);
            const void* gp = gB + kb + (size_t)i * 32 * K;
            asm volatile("cp.async.cg.shared.global [%0], [%1], 16;\n" ::"r"(dst), "l"(gp));
        }
    };

    fill(0, 0);
    asm volatile("cp.async.commit_group;\n" ::);

    for (int kt = 0; kt < KT; ++kt) {
        asm volatile("cp.async.wait_group 0;\n" ::);   // fill(kt) complete
        __syncthreads();                               // + compute(kt-1) done by all
        if (kt + 1 < KT) fill(kt + 1, (kt + 1) & 1);   // overlaps compute(kt)
        asm volatile("cp.async.commit_group;\n" ::);

        const uint32_t stb = sbase + (kt & 1) * STAGE_BYTES;
        const uint32_t aBase = stb + aRow0;
        const uint32_t bBase = stb + bRow0;
#pragma unroll
        for (int ks = 0; ks < 4; ++ks) {
            const uint32_t swoff = (uint32_t)(((2 * ks + hi) ^ rx) << 4);
            uint32_t af[4][4], bf[4][4];
#pragma unroll
            for (int i = 0; i < 4; i++) {
                uint32_t addr = aBase + swoff + i * (16 * 128);
                asm volatile("ldmatrix.sync.aligned.m8n8.x4.shared.b16 {%0,%1,%2,%3}, [%4];\n"
                             : "=r"(af[i][0]), "=r"(af[i][1]), "=r"(af[i][2]), "=r"(af[i][3])
                             : "r"(addr));
            }
#pragma unroll
            for (int jj = 0; jj < 4; jj++) {
                uint32_t addr = bBase + swoff + jj * (16 * 128);
                asm volatile("ldmatrix.sync.aligned.m8n8.x4.shared.b16 {%0,%1,%2,%3}, [%4];\n"
                             : "=r"(bf[jj][0]), "=r"(bf[jj][1]), "=r"(bf[jj][2]), "=r"(bf[jj][3])
                             : "r"(addr));
            }
#pragma unroll
            for (int i = 0; i < 4; i++) {
#pragma unroll
                for (int j = 0; j < 8; j++) {
                    const int jj = j >> 1, s = j & 1;
                    asm volatile(
                        "mma.sync.aligned.m16n8k32.row.col.f16.e4m3.e4m3.f16 "
                        "{%0,%1}, {%2,%3,%4,%5}, {%6,%7}, {%0,%1};\n"
                        : "+r"(acc[i][j][0]), "+r"(acc[i][j][1])
                        : "r"(af[i][0]), "r"(af[i][1]), "r"(af[i][2]), "r"(af[i][3]),
                          "r"(bf[jj][s]), "r"(bf[jj][s + 2]));
                }
            }
        }
    }

    // ----- epilogue -----
    if (EPI == 6) {
        // direct writes first
#pragma unroll
        for (int i = 0; i < 4; i++) {
            int rl = wm + i * 16 + (lane >> 2);
#pragma unroll
            for (int j = 0; j < 8; j++) {
                int cl = wn + j * 8 + (lane & 3) * 2;
#pragma unroll
                for (int h = 0; h < 2; h++) {
                    int rr = rl + h * 8;
                    __half2 hv = *(__half2*)&acc[i][j][h];
                    float v0 = __half2float(__low2half(hv)) * desc;
                    float v1 = __half2float(__high2half(hv)) * desc;
                    *(float2*)((float*)Cv + (size_t)(m0 + rr) * N + n0 + cl) =
                        make_float2(v0, v1);
                }
            }
        }
        // mirror via two 128-column staging passes (tb = 128 x 132 f32)
        float* tb = (float*)dynsm;
#pragma unroll 1
        for (int pass = 0; pass < 2; ++pass) {
            __syncthreads();                           // smem free / prev copy done
            if ((wn & 128) == pass * 128) {
#pragma unroll
                for (int i = 0; i < 4; i++) {
                    int rl = wm + i * 16 + (lane >> 2);
#pragma unroll
                    for (int j = 0; j < 8; j++) {
                        int cl = (wn & 63) + ((wn >> 6) & 1) * 64 + j * 8 + (lane & 3) * 2;
                        // local col within this 128-col pass:
                        int cll = (wn - pass * 128) + j * 8 + (lane & 3) * 2;
#pragma unroll
                        for (int h = 0; h < 2; h++) {
                            int rr = rl + h * 8;
                            __half2 hv = *(__half2*)&acc[i][j][h];
                            float v0 = __half2float(__low2half(hv)) * desc;
                            float v1 = __half2float(__high2half(hv)) * desc;
                            tb[cll * 132 + rr] = v0;
                            tb[(cll + 1) * 132 + rr] = v1;
                        }
                        (void)cl;
                    }
                }
            }
            __syncthreads();
            // coalesced mirror: sim[n0+pass*128+cl][m0 .. m0+128)
#pragma unroll
            for (int p = 0; p < 4; ++p) {
                int cl = (t >> 3) + p * 32;            // 0..127
                size_t gbase = (size_t)(n0 + pass * 128 + cl) * N + m0;
                const float* srow = tb + cl * 132;
#pragma unroll
                for (int k = 0; k < 4; ++k) {
                    int i4 = (t & 7) + 8 * k;          // 0..31 float4s
                    float4 v = *(const float4*)(srow + i4 * 4);
                    *(float4*)((float*)Cv + gbase + i4 * 4) = v;
                }
            }
        }
        return;
    }
#pragma unroll
    for (int i = 0; i < 4; i++) {
        int row0 = m0 + wm + i * 16 + (lane >> 2);
#pragma unroll
        for (int j = 0; j < 8; j++) {
            int col = n0 + wn + j * 8 + (lane & 3) * 2;
#pragma unroll
            for (int h = 0; h < 2; h++) {
                int r = row0 + h * 8;
                __half2 hv2 = *(__half2*)&acc[i][j][h];
                float v0 = __half2float(__low2half(hv2)) * desc;
                float v1 = __half2float(__high2half(hv2)) * desc;
                size_t off = (size_t)r * N + col;
                if (EPI == 0) {
                    *(float2*)((float*)Cv + off) = make_float2(v0, v1);
                } else if (EPI == 1) {
                    *(__nv_bfloat162*)((__nv_bfloat16*)Cv + off) =
                        __floats2bfloat162_rn(v0, v1);
                } else if (EPI == 2) {
                    uint16_t p = (uint16_t)f2e4m3(v0 * oscale) |
                                 ((uint16_t)f2e4m3(v1 * oscale) << 8);
                    *(uint16_t*)((uint8_t*)Cv + off) = p;
                } else if (EPI == 3) {
                    *(__nv_bfloat162*)((__nv_bfloat16*)Cv + off) =
                        __floats2bfloat162_rn(v0, v1);
                    uint16_t p = (uint16_t)f2e4m3(v0 * oscale) |
                                 ((uint16_t)f2e4m3(v1 * oscale) << 8);
                    *(uint16_t*)(out2 + (size_t)r * (2 * HH) + HH + col) = p;
                } else if (EPI == 4) {
                    float x0 = v0 + bias[col], x1 = v1 + bias[col + 1];
                    float g0 = 0.5f * x0 * (1.f + erff(x0 * 0.70710678118654752f));
                    float g1 = 0.5f * x1 * (1.f + erff(x1 * 0.70710678118654752f));
                    uint16_t p = (uint16_t)f2e4m3(g0 * oscale) |
                                 ((uint16_t)f2e4m3(g1 * oscale) << 8);
                    *(uint16_t*)((uint8_t*)Cv + off) = p;
                } else {
                    float x0 = v0 + bias[col], x1 = v1 + bias[col + 1];
                    float s0 = 1.f / (1.f + expf(-x0));
                    float s1 = 1.f / (1.f + expf(-x1));
                    __nv_bfloat162 cc = *(const __nv_bfloat162*)(crossp + off);
                    float2 hvv = *(const float2*)(hid + off);
                    *(float2*)((float*)Cv + off) =
                        make_float2(hvv.x + s0 * __bfloat162float(cc.x),
                                    hvv.y + s1 * __bfloat162float(cc.y));
                }
            }
        }
    }
}

// ---------------- host launcher ----------------
extern "C" void kernel_launch(void* const* d_in, const int* in_sizes, int n_in,
                              void* d_out, int out_size) {
    (void)in_sizes; (void)n_in; (void)out_size;
    const float* hidden = (const float*)d_in[0];
    const void*  amask  = d_in[1];
    const float* Wsim   = (const float*)d_in[2];
    const float* Wval   = (const float*)d_in[3];
    const float* Wg1    = (const float*)d_in[4];
    const float* bg1    = (const float*)d_in[5];
    const float* Wg2    = (const float*)d_in[6];
    const float* bg2    = (const float*)d_in[7];
    float* out = (float*)d_out;

    uint8_t *h8, *wsim8, *wval8, *wg18, *wg28, *normed8, *vals8, *valsT8, *wts8, *gin8, *h18;
    __nv_bfloat16 *proj, *cross;
    float* sim;
    unsigned char* mask;
    cudaGetSymbolAddress((void**)&h8,      g_hidden8);
    cudaGetSymbolAddress((void**)&wsim8,   g_Wsim8);
    cudaGetSymbolAddress((void**)&wval8,   g_Wval8);
    cudaGetSymbolAddress((void**)&wg18,    g_Wg18);
    cudaGetSymbolAddress((void**)&wg28,    g_Wg28);
    cudaGetSymbolAddress((void**)&proj,    g_proj_bf);
    cudaGetSymbolAddress((void**)&normed8, g_normed8);
    cudaGetSymbolAddress((void**)&vals8,   g_values8);
    cudaGetSymbolAddress((void**)&valsT8,  g_valuesT8);
    cudaGetSymbolAddress((void**)&sim,     g_sim_f32);
    cudaGetSymbolAddress((void**)&wts8,    g_weights8);
    cudaGetSymbolAddress((void**)&cross,   g_cross_bf);
    cudaGetSymbolAddress((void**)&gin8,    g_gatein8);
    cudaGetSymbolAddress((void**)&h18,     g_h18);
    cudaGetSymbolAddress((void**)&mask,    g_mask_u8);

    cudaFuncSetAttribute(gemm_nt_fp8<0>, cudaFuncAttributeMaxDynamicSharedMemorySize, GEMM_DYN_SMEM);
    cudaFuncSetAttribute(gemm_nt_fp8<1>, cudaFuncAttributeMaxDynamicSharedMemorySize, GEMM_DYN_SMEM);
    cudaFuncSetAttribute(gemm_nt_fp8<2>, cudaFuncAttributeMaxDynamicSharedMemorySize, GEMM_DYN_SMEM);
    cudaFuncSetAttribute(gemm_nt_fp8<3>, cudaFuncAttributeMaxDynamicSharedMemorySize, GEMM_DYN_SMEM);
    cudaFuncSetAttribute(gemm_nt_fp8<4>, cudaFuncAttributeMaxDynamicSharedMemorySize, GEMM_DYN_SMEM);
    cudaFuncSetAttribute(gemm_nt_fp8<5>, cudaFuncAttributeMaxDynamicSharedMemorySize, GEMM_DYN_SMEM);
    cudaFuncSetAttribute(gemm_nt_fp8<6>, cudaFuncAttributeMaxDynamicSharedMemorySize, GEMM_DYN_SMEM);

    // Launch order: ncu -s 5 -c 1 captures index 5 == sim GEMM (symmetric).
    // 0: fused mask
    mask_fused_kernel<<<1, 256>>>((const unsigned char*)amask, mask);
    // 1: hidden -> fp8 (x16) + gatein first half
    hidden_to_fp8_kernel<<<(unsigned)(((long)BB * HH / 4 + 255) / 256), 256>>>(hidden, h8, gin8);
    // 2: Wsim -> fp8 (x256)
    {
        long n4 = (long)HH * HH / 4;
        f32_to_fp8_kernel<<<(unsigned)((n4 + 255) / 256), 256>>>(Wsim, wsim8, 256.f, n4);
    }
    // 3: proj = hidden @ Wsim^T -> bf16   (desc 1/(16*256))
    gemm_nt_fp8<1><<<dim3(HH / 256, BB / 128), 256, GEMM_DYN_SMEM>>>(
        h8, wsim8, proj, BB, HH, HH, 1.f / 4096.f, 0.f, nullptr, nullptr, nullptr, nullptr);
    // 4: normalize -> normed fp8 (x64)
    normalize_rows_kernel<<<BB, 256>>>(proj, normed8);
    // 5: sim = normed @ normed^T -> f32, symmetric (desc 1/(64*64))  [ncu target]
    gemm_nt_fp8<6><<<dim3(BB / 256, BB / 128), 256, GEMM_DYN_SMEM>>>(
        normed8, normed8, sim, BB, BB, HH, 1.f / 4096.f, 0.f, nullptr, nullptr, nullptr, nullptr);
    // 6: Wval -> fp8 (x256)
    {
        long n4 = (long)HH * HH / 4;
        f32_to_fp8_kernel<<<(unsigned)((n4 + 255) / 256), 256>>>(Wval, wval8, 256.f, n4);
    }
    // 7: softmax -> weights fp8 (x16384)
    softmax_mask_kernel<<<BB, 256>>>(sim, mask, wts8);
    // 8: values = hidden @ Wval^T -> fp8 (x16)
    gemm_nt_fp8<2><<<dim3(HH / 256, BB / 128), 256, GEMM_DYN_SMEM>>>(
        h8, wval8, vals8, BB, HH, HH, 1.f / 4096.f, 16.f, nullptr, nullptr, nullptr, nullptr);
    // 9: transpose values -> valuesT
    transpose_u8_kernel<<<dim3(HH / 32, BB / 32), dim3(32, 8)>>>(vals8, valsT8, BB, HH);
    // 10: cross = weights @ values -> bf16 + fp8(x16) into gatein[:, H:2H]
    //     desc = 1/(16384*16)
    gemm_nt_fp8<3><<<dim3(HH / 256, BB / 128), 256, GEMM_DYN_SMEM>>>(
        wts8, valsT8, cross, BB, HH, BB, 1.f / 262144.f, 16.f, nullptr, nullptr, nullptr, gin8);
    // 11: Wg1 -> fp8 (x256)
    {
        long n4 = (long)GHH * 2 * HH / 4;
        f32_to_fp8_kernel<<<(unsigned)((n4 + 255) / 256), 256>>>(Wg1, wg18, 256.f, n4);
    }
    // 12: h1 = gelu(gatein @ Wg1^T + b1) -> fp8 (x64)   (desc 1/(16*256))
    gemm_nt_fp8<4><<<dim3(GHH / 256, BB / 128), 256, GEMM_DYN_SMEM>>>(
        gin8, wg18, h18, BB, GHH, 2 * HH, 1.f / 4096.f, 64.f, bg1, nullptr, nullptr, nullptr);
    // 13: Wg2 -> fp8 (x256)
    {
        long n4 = (long)HH * GHH / 4;
        f32_to_fp8_kernel<<<(unsigned)((n4 + 255) / 256), 256>>>(Wg2, wg28, 256.f, n4);
    }
    // 14: out = hidden + sigmoid(h1 @ Wg2^T + b2) * cross   (desc 1/(64*256))
    gemm_nt_fp8<5><<<dim3(HH / 256, BB / 128), 256, GEMM_DYN_SMEM>>>(
        h18, wg28, out, BB, HH, GHH, 1.f / 16384.f, 0.f, bg2, hidden, cross, nullptr);
}

// round 14
// speedup vs baseline: 1.0257x; 1.0257x over previous
#include <cuda_runtime.h>
#include <cuda_bf16.h>
#include <cuda_fp16.h>
#include <cuda_fp8.h>
#include <cstdint>
#include <math.h>

#define BB 8192
#define HH 4096
#define GHH 1024

// ---------------- scratch (device globals; allocation-free rule) ----------------
__device__ uint8_t       g_hidden8[(size_t)BB * HH];
__device__ uint8_t       g_Wsim8[(size_t)HH * HH];
__device__ uint8_t       g_Wval8[(size_t)HH * HH];
__device__ uint8_t       g_Wg18[(size_t)GHH * 2 * HH];
__device__ uint8_t       g_Wg28[(size_t)HH * GHH];
__device__ __nv_bfloat16 g_proj_bf[(size_t)BB * HH];
__device__ uint8_t       g_normed8[(size_t)BB * HH];
__device__ uint8_t       g_values8[(size_t)BB * HH];
__device__ uint8_t       g_valuesT8[(size_t)HH * BB];
__device__ float         g_sim_f32[(size_t)BB * BB];
__device__ uint8_t       g_weights8[(size_t)BB * BB];
__device__ __nv_bfloat16 g_cross_bf[(size_t)BB * HH];
__device__ uint8_t       g_gatein8[(size_t)BB * 2 * HH];
__device__ uint8_t       g_h18[(size_t)BB * GHH];
__device__ unsigned char g_mask_u8[BB];

// scales: hidden x16, W x256, normed x64, weights x16384, values x16, cross(gatein) x16, h1 x64

// ---------------- helpers ----------------
__device__ __forceinline__ uint32_t smem_u32(const void* p) {
    return (uint32_t)__cvta_generic_to_shared(p);
}
__device__ __forceinline__ uint8_t f2e4m3(float v) {
    return (uint8_t)__nv_cvt_float_to_fp8(v, __NV_SATFINITE, __NV_E4M3);
}

// ---------------- fused mask detect + expand (single block) ----------------
__global__ void mask_fused_kernel(const unsigned char* m, unsigned char* out) {
    __shared__ int s_nonbin, s_off4, s_fbad, s_bfbad, s_code;
    if (threadIdx.x == 0) { s_nonbin = 0; s_off4 = 0; s_fbad = 0; s_bfbad = 0; }
    __syncthreads();
    int nonbin = 0, off4 = 0, fbad = 0, bfbad = 0;
    for (int j = threadIdx.x; j < 8192; j += 256) {
        unsigned char b = m[j];
        if (b > 1) nonbin++;
        if ((j & 3) != 0 && b != 0) off4++;
    }
    const uint32_t* u = (const uint32_t*)m;
    for (int i = threadIdx.x; i < 2048; i += 256) {
        uint32_t w = u[i];
        if (!(w == 0u || w == 0x3f800000u)) fbad++;
    }
    const uint16_t* h = (const uint16_t*)m;
    for (int i = threadIdx.x; i < 4096; i += 256) {
        uint16_t x = h[i];
        if (!(x == 0 || x == 0x3f80)) bfbad++;
    }
    atomicAdd(&s_nonbin, nonbin);
    atomicAdd(&s_off4, off4);
    atomicAdd(&s_fbad, fbad);
    atomicAdd(&s_bfbad, bfbad);
    __syncthreads();
    if (threadIdx.x == 0) {
        int code;
        if (s_nonbin == 0) code = (s_off4 > 0) ? 0 : 1;
        else if (s_fbad == 0) code = 2;
        else if (s_bfbad == 0) code = 3;
        else code = 1;
        s_code = code;
    }
    __syncthreads();
    int code = s_code;
    for (int i = threadIdx.x; i < BB; i += 256) {
        bool v;
        if (code == 0)      v = ((const unsigned char*)m)[i] != 0;
        else if (code == 1) v = ((const int*)m)[i] != 0;
        else if (code == 2) v = ((const float*)m)[i] != 0.0f;
        else                v = (((const uint16_t*)m)[i] & 0x7fff) != 0;
        out[i] = v ? 1 : 0;
    }
}

// ---------------- fp32 -> fp8 convert (scale) ----------------
__global__ void f32_to_fp8_kernel(const float* __restrict__ in,
                                  uint8_t* __restrict__ out, float scale, long n4) {
    long i = (long)blockIdx.x * blockDim.x + threadIdx.x;
    if (i < n4) {
        float4 v = ((const float4*)in)[i];
        uint32_t p = (uint32_t)f2e4m3(v.x * scale) |
                     ((uint32_t)f2e4m3(v.y * scale) << 8) |
                     ((uint32_t)f2e4m3(v.z * scale) << 16) |
                     ((uint32_t)f2e4m3(v.w * scale) << 24);
        ((uint32_t*)out)[i] = p;
    }
}

// hidden -> g_hidden8 AND first half of g_gatein8, scale 16
__global__ void hidden_to_fp8_kernel(const float* __restrict__ in,
                                     uint8_t* __restrict__ out,
                                     uint8_t* __restrict__ gatein) {
    long i = ((long)blockIdx.x * blockDim.x + threadIdx.x);
    if (i >= (long)BB * HH / 4) return;
    float4 v = ((const float4*)in)[i];
    uint32_t p = (uint32_t)f2e4m3(v.x * 16.f) |
                 ((uint32_t)f2e4m3(v.y * 16.f) << 8) |
                 ((uint32_t)f2e4m3(v.z * 16.f) << 16) |
                 ((uint32_t)f2e4m3(v.w * 16.f) << 24);
    ((uint32_t*)out)[i] = p;
    long e = i * 4;
    long b = e >> 12;            // /HH
    int  j = (int)(e & (HH - 1));
    *(uint32_t*)(gatein + b * (2 * HH) + j) = p;
}

// ---------------- row L2 normalize: bf16 proj -> fp8 normed (x64) ----------------
__global__ void normalize_rows_kernel(const __nv_bfloat16* __restrict__ p,
                                      uint8_t* __restrict__ normed) {
    int row = blockIdx.x;
    const __nv_bfloat16* r = p + (size_t)row * HH;
    float s = 0.f;
    for (int j = threadIdx.x; j < HH; j += 256) {
        float v = __bfloat162float(r[j]);
        s += v * v;
    }
#pragma unroll
    for (int o = 16; o > 0; o >>= 1) s += __shfl_xor_sync(0xffffffffu, s, o);
    __shared__ float ws[8];
    int w = threadIdx.x >> 5, l = threadIdx.x & 31;
    if (l == 0) ws[w] = s;
    __syncthreads();
    if (threadIdx.x < 32) {
        float x = (threadIdx.x < 8) ? ws[threadIdx.x] : 0.f;
#pragma unroll
        for (int o = 4; o > 0; o >>= 1) x += __shfl_xor_sync(0xffffffffu, x, o);
        if (threadIdx.x == 0) ws[0] = x;
    }
    __syncthreads();
    float scale = 64.f / fmaxf(sqrtf(ws[0]), 1e-12f);
    uint8_t* nr = normed + (size_t)row * HH;
    for (int j = threadIdx.x; j < HH / 4; j += 256) {
        float v0 = __bfloat162float(r[j * 4 + 0]) * scale;
        float v1 = __bfloat162float(r[j * 4 + 1]) * scale;
        float v2 = __bfloat162float(r[j * 4 + 2]) * scale;
        float v3 = __bfloat162float(r[j * 4 + 3]) * scale;
        ((uint32_t*)nr)[j] = (uint32_t)f2e4m3(v0) | ((uint32_t)f2e4m3(v1) << 8) |
                             ((uint32_t)f2e4m3(v2) << 16) | ((uint32_t)f2e4m3(v3) << 24);
    }
}

// ---------------- masked softmax: f32 sim -> fp8 weights (x16384) ----------------
__global__ void softmax_mask_kernel(const float* __restrict__ sim,
                                    const unsigned char* __restrict__ mask,
                                    uint8_t* __restrict__ wts) {
    int row = blockIdx.x;
    __shared__ float sv[BB];
    __shared__ float red[8];
    const float* sr = sim + (size_t)row * BB;
    float mx = -INFINITY;
    for (int j = threadIdx.x; j < BB; j += 256) {
        float v = sr[j];
        if (j == row || mask[j] == 0) v = -INFINITY;
        sv[j] = v;
        mx = fmaxf(mx, v);
    }
#pragma unroll
    for (int o = 16; o > 0; o >>= 1) mx = fmaxf(mx, __shfl_xor_sync(0xffffffffu, mx, o));
    int w = threadIdx.x >> 5, l = threadIdx.x & 31;
    if (l == 0) red[w] = mx;
    __syncthreads();
    if (threadIdx.x < 32) {
        float x = (threadIdx.x < 8) ? red[threadIdx.x] : -INFINITY;
#pragma unroll
        for (int o = 4; o > 0; o >>= 1) x = fmaxf(x, __shfl_xor_sync(0xffffffffu, x, o));
        if (threadIdx.x == 0) red[0] = x;
    }
    __syncthreads();
    float M = red[0];
    __syncthreads();
    float sum = 0.f;
    for (int j = threadIdx.x; j < BB; j += 256) {
        float v = sv[j];
        float e = (v == -INFINITY) ? 0.f : __expf(v - M);
        sv[j] = e;
        sum += e;
    }
#pragma unroll
    for (int o = 16; o > 0; o >>= 1) sum += __shfl_xor_sync(0xffffffffu, sum, o);
    if (l == 0) red[w] = sum;
    __syncthreads();
    if (threadIdx.x < 32) {
        float x = (threadIdx.x < 8) ? red[threadIdx.x] : 0.f;
#pragma unroll
        for (int o = 4; o > 0; o >>= 1) x += __shfl_xor_sync(0xffffffffu, x, o);
        if (threadIdx.x == 0) red[0] = x;
    }
    __syncthreads();
    float S = red[0];
    float inv = (S > 0.f) ? 16384.f / S : 0.f;   // x16384 keeps f16 accumulators safe
    uint8_t* wr = wts + (size_t)row * BB;
    for (int j = threadIdx.x; j < BB / 4; j += 256) {
        ((uint32_t*)wr)[j] = (uint32_t)f2e4m3(sv[j * 4 + 0] * inv) |
                             ((uint32_t)f2e4m3(sv[j * 4 + 1] * inv) << 8) |
                             ((uint32_t)f2e4m3(sv[j * 4 + 2] * inv) << 16) |
                             ((uint32_t)f2e4m3(sv[j * 4 + 3] * inv) << 24);
    }
}

// ---------------- u8 transpose (values -> valuesT) ----------------
__global__ void transpose_u8_kernel(const uint8_t* __restrict__ in,
                                    uint8_t* __restrict__ out, int R, int C) {
    __shared__ uint8_t tile[32][33];
    int x = blockIdx.x * 32 + threadIdx.x;
    int y0 = blockIdx.y * 32 + threadIdx.y;
#pragma unroll
    for (int i = 0; i < 32; i += 8)
        tile[threadIdx.y + i][threadIdx.x] = in[(size_t)(y0 + i) * C + x];
    __syncthreads();
    int x2 = blockIdx.y * 32 + threadIdx.x;
    int y2 = blockIdx.x * 32 + threadIdx.y;
#pragma unroll
    for (int i = 0; i < 32; i += 8)
        out[(size_t)(y2 + i) * R + x2] = tile[threadIdx.x][threadIdx.y + i];
}

// ================= fp8 NT GEMM (mma.sync m16n8k32 e4m3, f16 accum) ==========
// C = A * B^T. CTA tile 128x128, warp tile 64x32 (8 warps 2Mx4N), K-stage 128B,
// XOR-swizzled smem, 2-stage cp.async pipeline (single sync/stage),
// 85-reg cap + 67.8KB smem -> 3 CTAs/SM (24 warps) with f16-acc register relief.
// EPI: 0=f32(desc), 1=bf16(desc), 2=fp8(desc*oscale),
//      3=cross: bf16 + fp8 into gatein second half,
//      4=gelu(desc*acc+bias)->fp8, 5=hid+sigmoid(desc*acc+bias)*cross->f32,
//      6=f32(desc) symmetric: skip above-diagonal tiles; mirror via smem stage
#define A_BYTES (128 * 128)                   // 16384
#define B_BYTES (128 * 128)                   // 16384
#define STAGE_BYTES (A_BYTES + B_BYTES)       // 32768
#define GEMM_DYN_SMEM 67840                   // >= max(2*STAGE+256, 128*132*4)

template <int EPI>
__global__ void __launch_bounds__(256, 3)
gemm_nt_fp8(const uint8_t* __restrict__ A,
            const uint8_t* __restrict__ Bm,
            void* __restrict__ Cv,
            int M, int N, int K,
            float desc, float oscale,
            const float* __restrict__ bias,
            const float* __restrict__ hid,
            const __nv_bfloat16* __restrict__ crossp,
            uint8_t* __restrict__ out2) {
    if (EPI == 6 && blockIdx.x > blockIdx.y) return;

    extern __shared__ char dynsm[];
    const uint32_t sbase = (smem_u32(dynsm) + 127u) & ~127u;

    const int t = threadIdx.x;
    const int warp = t >> 5, lane = t & 31;
    const int wm = (warp & 1) * 64;        // 2 warps over M
    const int wn = (warp >> 1) * 32;       // 4 warps over N
    const int m0 = blockIdx.y * 128;
    const int n0 = blockIdx.x * 128;
    const int KT = K >> 7;                 // 128-byte K stages

    // ---- producer addressing (XOR swizzle on 16B chunks) ----
    const int frow = t >> 3;
    const int fch = t & 7;
    const uint32_t swch = (uint32_t)(fch ^ (frow & 7)) * 16;
    const uint32_t sAoff = (uint32_t)frow * 128 + swch;
    const uint32_t sBoff = A_BYTES + (uint32_t)frow * 128 + swch;
    const uint8_t* gA = A + (size_t)(m0 + frow) * K + fch * 16;
    const uint8_t* gB = Bm + (size_t)(n0 + frow) * K + fch * 16;

    // ---- consumer addressing ----
    const int crow = lane & 15;
    const int hi = lane >> 4;
    const int rx = crow & 7;
    const uint32_t aRow0 = (uint32_t)(wm + crow) * 128;
    const uint32_t bRow0 = A_BYTES + (uint32_t)(wn + crow) * 128;

    // f16x2 accumulators: acc[i][j][h] holds cols (col,col+1) of row (base+h*8)
    uint32_t acc[4][4][2];
#pragma unroll
    for (int i = 0; i < 4; i++)
#pragma unroll
        for (int j = 0; j < 4; j++) { acc[i][j][0] = 0u; acc[i][j][1] = 0u; }

    auto fill = [&](int kt, int st) {
        const uint32_t stb = sbase + st * STAGE_BYTES;
        const size_t kb = (size_t)kt * 128;
#pragma unroll
        for (int i = 0; i < 4; i++) {
            uint32_t dst = stb + sAoff + i * (32 * 128);
            const void* gp = gA + kb + (size_t)i * 32 * K;
            asm volatile("cp.async.cg.shared.global [%0], [%1], 16;\n" ::"r"(dst), "l"(gp));
        }
#pragma unroll
        for (int i = 0; i < 4; i++) {
            uint32_t dst = stb + sBoff + i * (32 * 128);
            const void* gp = gB + kb + (size_t)i * 32 * K;
            asm volatile("cp.async.cg.shared.global [%0], [%1], 16;\n" ::"r"(dst), "l"(gp));
        }
    };

    fill(0, 0);
    asm volatile("cp.async.commit_group;\n" ::);

    for (int kt = 0; kt < KT; ++kt) {
        asm volatile("cp.async.wait_group 0;\n" ::);   // fill(kt) complete
        __syncthreads();                               // + compute(kt-1) done by all
        if (kt + 1 < KT) fill(kt + 1, (kt + 1) & 1);   // overlaps compute(kt)
        asm volatile("cp.async.commit_group;\n" ::);

        const uint32_t stb = sbase + (kt & 1) * STAGE_BYTES;
        const uint32_t aBase = stb + aRow0;
        const uint32_t bBase = stb + bRow0;
#pragma unroll
        for (int ks = 0; ks < 4; ++ks) {
            const uint32_t swoff = (uint32_t)(((2 * ks + hi) ^ rx) << 4);
            uint32_t af[4][4], bf[2][4];
#pragma unroll
            for (int i = 0; i < 4; i++) {
                uint32_t addr = aBase + swoff + i * (16 * 128);
                asm volatile("ldmatrix.sync.aligned.m8n8.x4.shared.b16 {%0,%1,%2,%3}, [%4];\n"
                             : "=r"(af[i][0]), "=r"(af[i][1]), "=r"(af[i][2]), "=r"(af[i][3])
                             : "r"(addr));
            }
#pragma unroll
            for (int jj = 0; jj < 2; jj++) {
                uint32_t addr = bBase + swoff + jj * (16 * 128);
                asm volatile("ldmatrix.sync.aligned.m8n8.x4.shared.b16 {%0,%1,%2,%3}, [%4];\n"
                             : "=r"(bf[jj][0]), "=r"(bf[jj][1]), "=r"(bf[jj][2]), "=r"(bf[jj][3])
                             : "r"(addr));
            }
#pragma unroll
            for (int i = 0; i < 4; i++) {
#pragma unroll
                for (int j = 0; j < 4; j++) {
                    const int jj = j >> 1, s = j & 1;
                    asm volatile(
                        "mma.sync.aligned.m16n8k32.row.col.f16.e4m3.e4m3.f16 "
                        "{%0,%1}, {%2,%3,%4,%5}, {%6,%7}, {%0,%1};\n"
                        : "+r"(acc[i][j][0]), "+r"(acc[i][j][1])
                        : "r"(af[i][0]), "r"(af[i][1]), "r"(af[i][2]), "r"(af[i][3]),
                          "r"(bf[jj][s]), "r"(bf[jj][s + 2]));
                }
            }
        }
    }

    // ----- epilogue -----
    if (EPI == 6) {
        __syncthreads();                       // pipeline smem is dead now
        float* tb = (float*)dynsm;             // 128 x 132 f32 staging
#pragma unroll
        for (int i = 0; i < 4; i++) {
            int rl = wm + i * 16 + (lane >> 2);
#pragma unroll
            for (int j = 0; j < 4; j++) {
                int cl = wn + j * 8 + (lane & 3) * 2;
#pragma unroll
                for (int h = 0; h < 2; h++) {
                    int rr = rl + h * 8;
                    __half2 hv = *(__half2*)&acc[i][j][h];
                    float v0 = __half2float(__low2half(hv)) * desc;
                    float v1 = __half2float(__high2half(hv)) * desc;
                    *(float2*)((float*)Cv + (size_t)(m0 + rr) * N + n0 + cl) =
                        make_float2(v0, v1);
                    tb[cl * 132 + rr] = v0;
                    tb[(cl + 1) * 132 + rr] = v1;
                }
            }
        }
        __syncthreads();
#pragma unroll
        for (int p = 0; p < 4; ++p) {
            int cl = (t >> 3) + p * 32;
            size_t gbase = (size_t)(n0 + cl) * N + m0;
            const float* srow = tb + cl * 132;
#pragma unroll
            for (int k = 0; k < 4; ++k) {
                int i4 = (t & 7) + 8 * k;
                float4 v = *(const float4*)(srow + i4 * 4);
                *(float4*)((float*)Cv + gbase + i4 * 4) = v;
            }
        }
        return;
    }
#pragma unroll
    for (int i = 0; i < 4; i++) {
        int row0 = m0 + wm + i * 16 + (lane >> 2);
#pragma unroll
        for (int j = 0; j < 4; j++) {
            int col = n0 + wn + j * 8 + (lane & 3) * 2;
#pragma unroll
            for (int h = 0; h < 2; h++) {
                int r = row0 + h * 8;
                __half2 hv2 = *(__half2*)&acc[i][j][h];
                float v0 = __half2float(__low2half(hv2)) * desc;
                float v1 = __half2float(__high2half(hv2)) * desc;
                size_t off = (size_t)r * N + col;
                if (EPI == 0) {
                    *(float2*)((float*)Cv + off) = make_float2(v0, v1);
                } else if (EPI == 1) {
                    *(__nv_bfloat162*)((__nv_bfloat16*)Cv + off) =
                        __floats2bfloat162_rn(v0, v1);
                } else if (EPI == 2) {
                    uint16_t p = (uint16_t)f2e4m3(v0 * oscale) |
                                 ((uint16_t)f2e4m3(v1 * oscale) << 8);
                    *(uint16_t*)((uint8_t*)Cv + off) = p;
                } else if (EPI == 3) {
                    *(__nv_bfloat162*)((__nv_bfloat16*)Cv + off) =
                        __floats2bfloat162_rn(v0, v1);
                    uint16_t p = (uint16_t)f2e4m3(v0 * oscale) |
                                 ((uint16_t)f2e4m3(v1 * oscale) << 8);
                    *(uint16_t*)(out2 + (size_t)r * (2 * HH) + HH + col) = p;
                } else if (EPI == 4) {
                    float x0 = v0 + bias[col], x1 = v1 + bias[col + 1];
                    float g0 = 0.5f * x0 * (1.f + erff(x0 * 0.70710678118654752f));
                    float g1 = 0.5f * x1 * (1.f + erff(x1 * 0.70710678118654752f));
                    uint16_t p = (uint16_t)f2e4m3(g0 * oscale) |
                                 ((uint16_t)f2e4m3(g1 * oscale) << 8);
                    *(uint16_t*)((uint8_t*)Cv + off) = p;
                } else {
                    float x0 = v0 + bias[col], x1 = v1 + bias[col + 1];
                    float s0 = 1.f / (1.f + expf(-x0));
                    float s1 = 1.f / (1.f + expf(-x1));
                    __nv_bfloat162 cc = *(const __nv_bfloat162*)(crossp + off);
                    float2 hvv = *(const float2*)(hid + off);
                    *(float2*)((float*)Cv + off) =
                        make_float2(hvv.x + s0 * __bfloat162float(cc.x),
                                    hvv.y + s1 * __bfloat162float(cc.y));
                }
            }
        }
    }
}

// ---------------- host launcher ----------------
extern "C" void kernel_launch(void* const* d_in, const int* in_sizes, int n_in,
                              void* d_out, int out_size) {
    (void)in_sizes; (void)n_in; (void)out_size;
    const float* hidden = (const float*)d_in[0];
    const void*  amask  = d_in[1];
    const float* Wsim   = (const float*)d_in[2];
    const float* Wval   = (const float*)d_in[3];
    const float* Wg1    = (const float*)d_in[4];
    const float* bg1    = (const float*)d_in[5];
    const float* Wg2    = (const float*)d_in[6];
    const float* bg2    = (const float*)d_in[7];
    float* out = (float*)d_out;

    uint8_t *h8, *wsim8, *wval8, *wg18, *wg28, *normed8, *vals8, *valsT8, *wts8, *gin8, *h18;
    __nv_bfloat16 *proj, *cross;
    float* sim;
    unsigned char* mask;
    cudaGetSymbolAddress((void**)&h8,      g_hidden8);
    cudaGetSymbolAddress((void**)&wsim8,   g_Wsim8);
    cudaGetSymbolAddress((void**)&wval8,   g_Wval8);
    cudaGetSymbolAddress((void**)&wg18,    g_Wg18);
    cudaGetSymbolAddress((void**)&wg28,    g_Wg28);
    cudaGetSymbolAddress((void**)&proj,    g_proj_bf);
    cudaGetSymbolAddress((void**)&normed8, g_normed8);
    cudaGetSymbolAddress((void**)&vals8,   g_values8);
    cudaGetSymbolAddress((void**)&valsT8,  g_valuesT8);
    cudaGetSymbolAddress((void**)&sim,     g_sim_f32);
    cudaGetSymbolAddress((void**)&wts8,    g_weights8);
    cudaGetSymbolAddress((void**)&cross,   g_cross_bf);
    cudaGetSymbolAddress((void**)&gin8,    g_gatein8);
    cudaGetSymbolAddress((void**)&h18,     g_h18);
    cudaGetSymbolAddress((void**)&mask,    g_mask_u8);

    cudaFuncSetAttribute(gemm_nt_fp8<0>, cudaFuncAttributeMaxDynamicSharedMemorySize, GEMM_DYN_SMEM);
    cudaFuncSetAttribute(gemm_nt_fp8<1>, cudaFuncAttributeMaxDynamicSharedMemorySize, GEMM_DYN_SMEM);
    cudaFuncSetAttribute(gemm_nt_fp8<2>, cudaFuncAttributeMaxDynamicSharedMemorySize, GEMM_DYN_SMEM);
    cudaFuncSetAttribute(gemm_nt_fp8<3>, cudaFuncAttributeMaxDynamicSharedMemorySize, GEMM_DYN_SMEM);
    cudaFuncSetAttribute(gemm_nt_fp8<4>, cudaFuncAttributeMaxDynamicSharedMemorySize, GEMM_DYN_SMEM);
    cudaFuncSetAttribute(gemm_nt_fp8<5>, cudaFuncAttributeMaxDynamicSharedMemorySize, GEMM_DYN_SMEM);
    cudaFuncSetAttribute(gemm_nt_fp8<6>, cudaFuncAttributeMaxDynamicSharedMemorySize, GEMM_DYN_SMEM);

    // Launch order: ncu -s 5 -c 1 captures index 5 == sim GEMM (symmetric).
    // 0: fused mask
    mask_fused_kernel<<<1, 256>>>((const unsigned char*)amask, mask);
    // 1: hidden -> fp8 (x16) + gatein first half
    hidden_to_fp8_kernel<<<(unsigned)(((long)BB * HH / 4 + 255) / 256), 256>>>(hidden, h8, gin8);
    // 2: Wsim -> fp8 (x256)
    {
        long n4 = (long)HH * HH / 4;
        f32_to_fp8_kernel<<<(unsigned)((n4 + 255) / 256), 256>>>(Wsim, wsim8, 256.f, n4);
    }
    // 3: proj = hidden @ Wsim^T -> bf16   (desc 1/(16*256))
    gemm_nt_fp8<1><<<dim3(HH / 128, BB / 128), 256, GEMM_DYN_SMEM>>>(
        h8, wsim8, proj, BB, HH, HH, 1.f / 4096.f, 0.f, nullptr, nullptr, nullptr, nullptr);
    // 4: normalize -> normed fp8 (x64)
    normalize_rows_kernel<<<BB, 256>>>(proj, normed8);
    // 5: sim = normed @ normed^T -> f32, symmetric (desc 1/(64*64))  [ncu target]
    gemm_nt_fp8<6><<<dim3(BB / 128, BB / 128), 256, GEMM_DYN_SMEM>>>(
        normed8, normed8, sim, BB, BB, HH, 1.f / 4096.f, 0.f, nullptr, nullptr, nullptr, nullptr);
    // 6: Wval -> fp8 (x256)
    {
        long n4 = (long)HH * HH / 4;
        f32_to_fp8_kernel<<<(unsigned)((n4 + 255) / 256), 256>>>(Wval, wval8, 256.f, n4);
    }
    // 7: softmax -> weights fp8 (x16384)
    softmax_mask_kernel<<<BB, 256>>>(sim, mask, wts8);
    // 8: values = hidden @ Wval^T -> fp8 (x16)
    gemm_nt_fp8<2><<<dim3(HH / 128, BB / 128), 256, GEMM_DYN_SMEM>>>(
        h8, wval8, vals8, BB, HH, HH, 1.f / 4096.f, 16.f, nullptr, nullptr, nullptr, nullptr);
    // 9: transpose values -> valuesT
    transpose_u8_kernel<<<dim3(HH / 32, BB / 32), dim3(32, 8)>>>(vals8, valsT8, BB, HH);
    // 10: cross = weights @ values -> bf16 + fp8(x16) into gatein[:, H:2H]
    //     desc = 1/(16384*16)
    gemm_nt_fp8<3><<<dim3(HH / 128, BB / 128), 256, GEMM_DYN_SMEM>>>(
        wts8, valsT8, cross, BB, HH, BB, 1.f / 262144.f, 16.f, nullptr, nullptr, nullptr, gin8);
    // 11: Wg1 -> fp8 (x256)
    {
        long n4 = (long)GHH * 2 * HH / 4;
        f32_to_fp8_kernel<<<(unsigned)((n4 + 255) / 256), 256>>>(Wg1, wg18, 256.f, n4);
    }
    // 12: h1 = gelu(gatein @ Wg1^T + b1) -> fp8 (x64)   (desc 1/(16*256))
    gemm_nt_fp8<4><<<dim3(GHH / 128, BB / 128), 256, GEMM_DYN_SMEM>>>(
        gin8, wg18, h18, BB, GHH, 2 * HH, 1.f / 4096.f, 64.f, bg1, nullptr, nullptr, nullptr);
    // 13: Wg2 -> fp8 (x256)
    {
        long n4 = (long)HH * GHH / 4;
        f32_to_fp8_kernel<<<(unsigned)((n4 + 255) / 256), 256>>>(Wg2, wg28, 256.f, n4);
    }
    // 14: out = hidden + sigmoid(h1 @ Wg2^T + b2) * cross   (desc 1/(64*256))
    gemm_nt_fp8<5><<<dim3(HH / 128, BB / 128), 256, GEMM_DYN_SMEM>>>(
        h18, wg28, out, BB, HH, GHH, 1.f / 16384.f, 0.f, bg2, hidden, cross, nullptr);
}

// round 15
// speedup vs baseline: 1.2195x; 1.1889x over previous
#include <cuda_runtime.h>
#include <cuda_bf16.h>
#include <cuda_fp16.h>
#include <cuda_fp8.h>
#include <cstdint>
#include <math.h>

#define BB 8192
#define HH 4096
#define GHH 1024

// ---------------- scratch (device globals; allocation-free rule) ----------------
__device__ uint8_t       g_hidden8[(size_t)BB * HH];
__device__ uint8_t       g_Wsim8[(size_t)HH * HH];
__device__ uint8_t       g_Wval8[(size_t)HH * HH];
__device__ uint8_t       g_Wg18[(size_t)GHH * 2 * HH];
__device__ uint8_t       g_Wg28[(size_t)HH * GHH];
__device__ __nv_bfloat16 g_proj_bf[(size_t)BB * HH];
__device__ uint8_t       g_normed8[(size_t)BB * HH];
__device__ uint8_t       g_normedC8[(size_t)BB * HH];   // compacted valid rows
__device__ uint8_t       g_values8[(size_t)BB * HH];
__device__ uint8_t       g_valuesC8[(size_t)BB * HH];   // compacted valid rows
__device__ uint8_t       g_valuesT8[(size_t)HH * BB];   // transpose of compacted
__device__ float         g_sim_f32[(size_t)BB * BB];
__device__ uint8_t       g_weights8[(size_t)BB * BB];   // compacted cols, stride BB
__device__ __nv_bfloat16 g_cross_bf[(size_t)BB * HH];
__device__ uint8_t       g_gatein8[(size_t)BB * 2 * HH];
__device__ uint8_t       g_h18[(size_t)BB * GHH];
__device__ unsigned char g_mask_u8[BB];
__device__ int           g_cidx[BB];
__device__ int           g_selfpos[BB];
__device__ int           g_nvals[2];                    // [0]=nv, [1]=nvp (pad 128)

// scales: hidden x16, W x256, normed x64, weights x16384, values x16, cross x16, h1 x64

// ---------------- helpers ----------------
__device__ __forceinline__ uint32_t smem_u32(const void* p) {
    return (uint32_t)__cvta_generic_to_shared(p);
}
__device__ __forceinline__ uint8_t f2e4m3(float v) {
    return (uint8_t)__nv_cvt_float_to_fp8(v, __NV_SATFINITE, __NV_E4M3);
}

// ---------------- mask detect + expand + compact (single block) --------------
__global__ void mask_compact_kernel(const unsigned char* m, unsigned char* out,
                                    int* cidx, int* selfpos, int* nvals) {
    __shared__ int s_nonbin, s_off4, s_fbad, s_bfbad, s_code;
    __shared__ int cnt[257];
    const int t = threadIdx.x;
    if (t == 0) { s_nonbin = 0; s_off4 = 0; s_fbad = 0; s_bfbad = 0; }
    __syncthreads();
    int nonbin = 0, off4 = 0, fbad = 0, bfbad = 0;
    for (int j = t; j < 8192; j += 256) {
        unsigned char b = m[j];
        if (b > 1) nonbin++;
        if ((j & 3) != 0 && b != 0) off4++;
    }
    const uint32_t* u = (const uint32_t*)m;
    for (int i = t; i < 2048; i += 256) {
        uint32_t w = u[i];
        if (!(w == 0u || w == 0x3f800000u)) fbad++;
    }
    const uint16_t* h = (const uint16_t*)m;
    for (int i = t; i < 4096; i += 256) {
        uint16_t x = h[i];
        if (!(x == 0 || x == 0x3f80)) bfbad++;
    }
    atomicAdd(&s_nonbin, nonbin);
    atomicAdd(&s_off4, off4);
    atomicAdd(&s_fbad, fbad);
    atomicAdd(&s_bfbad, bfbad);
    __syncthreads();
    if (t == 0) {
        int code;
        if (s_nonbin == 0) code = (s_off4 > 0) ? 0 : 1;
        else if (s_fbad == 0) code = 2;
        else if (s_bfbad == 0) code = 3;
        else code = 1;
        s_code = code;
    }
    __syncthreads();
    const int code = s_code;

    // each thread owns 32 consecutive indices
    bool vloc[32];
    int c = 0;
#pragma unroll
    for (int e = 0; e < 32; e++) {
        int i = t * 32 + e;
        bool v;
        if (code == 0)      v = ((const unsigned char*)m)[i] != 0;
        else if (code == 1) v = ((const int*)m)[i] != 0;
        else if (code == 2) v = ((const float*)m)[i] != 0.0f;
        else                v = (((const uint16_t*)m)[i] & 0x7fff) != 0;
        vloc[e] = v;
        out[i] = v ? 1 : 0;
        c += v ? 1 : 0;
    }
    cnt[t] = c;
    __syncthreads();
    if (t == 0) {
        int run = 0;
        for (int i = 0; i < 256; i++) { int x = cnt[i]; cnt[i] = run; run += x; }
        cnt[256] = run;
        nvals[0] = run;
        nvals[1] = (run + 127) & ~127;
    }
    __syncthreads();
    int pos = cnt[t];
#pragma unroll
    for (int e = 0; e < 32; e++) {
        int i = t * 32 + e;
        if (vloc[e]) { cidx[pos] = i; selfpos[i] = pos; pos++; }
        else selfpos[i] = -1;
    }
}

// ---------------- row gather (compaction): dst[r] = src[cidx[r]], zero pad ----
__global__ void gather_rows_kernel(const uint8_t* __restrict__ src,
                                   uint8_t* __restrict__ dst,
                                   const int* __restrict__ cidx,
                                   const int* __restrict__ nvals, int C) {
    int row = blockIdx.x;
    int nv = nvals[0], nvp = nvals[1];
    if (row >= nvp) return;
    uint4* d = (uint4*)(dst + (size_t)row * C);
    if (row < nv) {
        const uint4* s = (const uint4*)(src + (size_t)cidx[row] * C);
        for (int j = threadIdx.x; j < C / 16; j += blockDim.x) d[j] = s[j];
    } else {
        uint4 z = make_uint4(0, 0, 0, 0);
        for (int j = threadIdx.x; j < C / 16; j += blockDim.x) d[j] = z;
    }
}

// ---------------- fp32 -> fp8 convert (scale) ----------------
__global__ void f32_to_fp8_kernel(const float* __restrict__ in,
                                  uint8_t* __restrict__ out, float scale, long n4) {
    long i = (long)blockIdx.x * blockDim.x + threadIdx.x;
    if (i < n4) {
        float4 v = ((const float4*)in)[i];
        uint32_t p = (uint32_t)f2e4m3(v.x * scale) |
                     ((uint32_t)f2e4m3(v.y * scale) << 8) |
                     ((uint32_t)f2e4m3(v.z * scale) << 16) |
                     ((uint32_t)f2e4m3(v.w * scale) << 24);
        ((uint32_t*)out)[i] = p;
    }
}

// hidden -> g_hidden8 AND first half of g_gatein8, scale 16
__global__ void hidden_to_fp8_kernel(const float* __restrict__ in,
                                     uint8_t* __restrict__ out,
                                     uint8_t* __restrict__ gatein) {
    long i = ((long)blockIdx.x * blockDim.x + threadIdx.x);
    if (i >= (long)BB * HH / 4) return;
    float4 v = ((const float4*)in)[i];
    uint32_t p = (uint32_t)f2e4m3(v.x * 16.f) |
                 ((uint32_t)f2e4m3(v.y * 16.f) << 8) |
                 ((uint32_t)f2e4m3(v.z * 16.f) << 16) |
                 ((uint32_t)f2e4m3(v.w * 16.f) << 24);
    ((uint32_t*)out)[i] = p;
    long e = i * 4;
    long b = e >> 12;
    int  j = (int)(e & (HH - 1));
    *(uint32_t*)(gatein + b * (2 * HH) + j) = p;
}

// ---------------- row L2 normalize: bf16 proj -> fp8 normed (x64) ----------------
__global__ void normalize_rows_kernel(const __nv_bfloat16* __restrict__ p,
                                      uint8_t* __restrict__ normed) {
    int row = blockIdx.x;
    const __nv_bfloat16* r = p + (size_t)row * HH;
    float s = 0.f;
    for (int j = threadIdx.x; j < HH; j += 256) {
        float v = __bfloat162float(r[j]);
        s += v * v;
    }
#pragma unroll
    for (int o = 16; o > 0; o >>= 1) s += __shfl_xor_sync(0xffffffffu, s, o);
    __shared__ float ws[8];
    int w = threadIdx.x >> 5, l = threadIdx.x & 31;
    if (l == 0) ws[w] = s;
    __syncthreads();
    if (threadIdx.x < 32) {
        float x = (threadIdx.x < 8) ? ws[threadIdx.x] : 0.f;
#pragma unroll
        for (int o = 4; o > 0; o >>= 1) x += __shfl_xor_sync(0xffffffffu, x, o);
        if (threadIdx.x == 0) ws[0] = x;
    }
    __syncthreads();
    float scale = 64.f / fmaxf(sqrtf(ws[0]), 1e-12f);
    uint8_t* nr = normed + (size_t)row * HH;
    for (int j = threadIdx.x; j < HH / 4; j += 256) {
        float v0 = __bfloat162float(r[j * 4 + 0]) * scale;
        float v1 = __bfloat162float(r[j * 4 + 1]) * scale;
        float v2 = __bfloat162float(r[j * 4 + 2]) * scale;
        float v3 = __bfloat162float(r[j * 4 + 3]) * scale;
        ((uint32_t*)nr)[j] = (uint32_t)f2e4m3(v0) | ((uint32_t)f2e4m3(v1) << 8) |
                             ((uint32_t)f2e4m3(v2) << 16) | ((uint32_t)f2e4m3(v3) << 24);
    }
}

// ------- masked softmax over compacted sim: f32 -> fp8 weights (x16384) -------
__global__ void softmax_mask_kernel(const float* __restrict__ sim,
                                    const int* __restrict__ selfpos,
                                    const int* __restrict__ nvals,
                                    uint8_t* __restrict__ wts) {
    int row = blockIdx.x;
    int nv = nvals[0], nvp = nvals[1];
    int sp = selfpos[row];
    __shared__ float sv[BB];
    __shared__ float red[8];
    const float* sr = sim + (size_t)row * BB;
    float mx = -INFINITY;
    for (int j = threadIdx.x; j < nv; j += 256) {
        float v = (j == sp) ? -INFINITY : sr[j];
        sv[j] = v;
        mx = fmaxf(mx, v);
    }
#pragma unroll
    for (int o = 16; o > 0; o >>= 1) mx = fmaxf(mx, __shfl_xor_sync(0xffffffffu, mx, o));
    int w = threadIdx.x >> 5, l = threadIdx.x & 31;
    if (l == 0) red[w] = mx;
    __syncthreads();
    if (threadIdx.x < 32) {
        float x = (threadIdx.x < 8) ? red[threadIdx.x] : -INFINITY;
#pragma unroll
        for (int o = 4; o > 0; o >>= 1) x = fmaxf(x, __shfl_xor_sync(0xffffffffu, x, o));
        if (threadIdx.x == 0) red[0] = x;
    }
    __syncthreads();
    float M = red[0];
    __syncthreads();
    float sum = 0.f;
    for (int j = threadIdx.x; j < nv; j += 256) {
        float v = sv[j];
        float e = (v == -INFINITY) ? 0.f : __expf(v - M);
        sv[j] = e;
        sum += e;
    }
#pragma unroll
    for (int o = 16; o > 0; o >>= 1) sum += __shfl_xor_sync(0xffffffffu, sum, o);
    if (l == 0) red[w] = sum;
    __syncthreads();
    if (threadIdx.x < 32) {
        float x = (threadIdx.x < 8) ? red[threadIdx.x] : 0.f;
#pragma unroll
        for (int o = 4; o > 0; o >>= 1) x += __shfl_xor_sync(0xffffffffu, x, o);
        if (threadIdx.x == 0) red[0] = x;
    }
    __syncthreads();
    float S = red[0];
    float inv = (S > 0.f) ? 16384.f / S : 0.f;
    uint8_t* wr = wts + (size_t)row * BB;
    for (int j = threadIdx.x; j < nvp; j += 256)
        wr[j] = (j < nv) ? f2e4m3(sv[j] * inv) : (uint8_t)0;
}

// ---------------- u8 transpose (valuesC -> valuesT) ----------------
__global__ void transpose_u8_kernel(const uint8_t* __restrict__ in,
                                    uint8_t* __restrict__ out, int R, int C) {
    __shared__ uint8_t tile[32][33];
    int x = blockIdx.x * 32 + threadIdx.x;
    int y0 = blockIdx.y * 32 + threadIdx.y;
#pragma unroll
    for (int i = 0; i < 32; i += 8)
        tile[threadIdx.y + i][threadIdx.x] = in[(size_t)(y0 + i) * C + x];
    __syncthreads();
    int x2 = blockIdx.y * 32 + threadIdx.x;
    int y2 = blockIdx.x * 32 + threadIdx.y;
#pragma unroll
    for (int i = 0; i < 32; i += 8)
        out[(size_t)(y2 + i) * R + x2] = tile[threadIdx.x][threadIdx.y + i];
}

// ================= fp8 NT GEMM (mma.sync m16n8k32 e4m3, f16 accum) ==========
// C[M,N] = A[M,K] * B[N,K]^T, lda/ldb row strides (bytes).
// dynk:   if non-null, effective K = dynk[1] (nvp, mult of 128).
// dyncol: if non-null, CTAs with n0 >= dyncol[1] exit (compacted N).
// CTA 128x128, warp 64x32, 2-stage cp.async, XOR swizzle, 3 CTAs/SM, f16 acc.
// EPI: 0=f32(desc), 1=bf16(desc), 2=fp8(desc*oscale),
//      3=cross: bf16 + fp8 into gatein second half,
//      4=gelu(desc*acc+bias)->fp8, 5=hid+sigmoid(desc*acc+bias)*cross->f32
#define A_BYTES (128 * 128)
#define B_BYTES (128 * 128)
#define STAGE_BYTES (A_BYTES + B_BYTES)
#define GEMM_DYN_SMEM (2 * STAGE_BYTES + 256)

template <int EPI>
__global__ void __launch_bounds__(256, 3)
gemm_nt_fp8(const uint8_t* __restrict__ A,
            const uint8_t* __restrict__ Bm,
            void* __restrict__ Cv,
            int M, int N, int K, int lda, int ldb,
            float desc, float oscale,
            const float* __restrict__ bias,
            const float* __restrict__ hid,
            const __nv_bfloat16* __restrict__ crossp,
            uint8_t* __restrict__ out2,
            const int* __restrict__ dynk,
            const int* __restrict__ dyncol) {
    const int n0 = blockIdx.x * 128;
    if (dyncol && n0 >= dyncol[1]) return;
    const int Keff = dynk ? dynk[1] : K;
    const int KT = Keff >> 7;

    extern __shared__ char dynsm[];
    const uint32_t sbase = (smem_u32(dynsm) + 127u) & ~127u;

    const int t = threadIdx.x;
    const int warp = t >> 5, lane = t & 31;
    const int wm = (warp & 1) * 64;
    const int wn = (warp >> 1) * 32;
    const int m0 = blockIdx.y * 128;

    // ---- producer addressing (XOR swizzle on 16B chunks) ----
    const int frow = t >> 3;
    const int fch = t & 7;
    const uint32_t swch = (uint32_t)(fch ^ (frow & 7)) * 16;
    const uint32_t sAoff = (uint32_t)frow * 128 + swch;
    const uint32_t sBoff = A_BYTES + (uint32_t)frow * 128 + swch;
    const uint8_t* gA = A + (size_t)(m0 + frow) * lda + fch * 16;
    const uint8_t* gB = Bm + (size_t)(n0 + frow) * ldb + fch * 16;

    // ---- consumer addressing ----
    const int crow = lane & 15;
    const int hi = lane >> 4;
    const int rx = crow & 7;
    const uint32_t aRow0 = (uint32_t)(wm + crow) * 128;
    const uint32_t bRow0 = A_BYTES + (uint32_t)(wn + crow) * 128;

    uint32_t acc[4][4][2];
#pragma unroll
    for (int i = 0; i < 4; i++)
#pragma unroll
        for (int j = 0; j < 4; j++) { acc[i][j][0] = 0u; acc[i][j][1] = 0u; }

    auto fill = [&](int kt, int st) {
        const uint32_t stb = sbase + st * STAGE_BYTES;
        const size_t kb = (size_t)kt * 128;
#pragma unroll
        for (int i = 0; i < 4; i++) {
            uint32_t dst = stb + sAoff + i * (32 * 128);
            const void* gp = gA + kb + (size_t)i * 32 * lda;
            asm volatile("cp.async.cg.shared.global [%0], [%1], 16;\n" ::"r"(dst), "l"(gp));
        }
#pragma unroll
        for (int i = 0; i < 4; i++) {
            uint32_t dst = stb + sBoff + i * (32 * 128);
            const void* gp = gB + kb + (size_t)i * 32 * ldb;
            asm volatile("cp.async.cg.shared.global [%0], [%1], 16;\n" ::"r"(dst), "l"(gp));
        }
    };

    if (KT > 0) {
        fill(0, 0);
        asm volatile("cp.async.commit_group;\n" ::);
    }

    for (int kt = 0; kt < KT; ++kt) {
        asm volatile("cp.async.wait_group 0;\n" ::);
        __syncthreads();
        if (kt + 1 < KT) fill(kt + 1, (kt + 1) & 1);
        asm volatile("cp.async.commit_group;\n" ::);

        const uint32_t stb = sbase + (kt & 1) * STAGE_BYTES;
        const uint32_t aBase = stb + aRow0;
        const uint32_t bBase = stb + bRow0;
#pragma unroll
        for (int ks = 0; ks < 4; ++ks) {
            const uint32_t swoff = (uint32_t)(((2 * ks + hi) ^ rx) << 4);
            uint32_t af[4][4], bf[2][4];
#pragma unroll
            for (int i = 0; i < 4; i++) {
                uint32_t addr = aBase + swoff + i * (16 * 128);
                asm volatile("ldmatrix.sync.aligned.m8n8.x4.shared.b16 {%0,%1,%2,%3}, [%4];\n"
                             : "=r"(af[i][0]), "=r"(af[i][1]), "=r"(af[i][2]), "=r"(af[i][3])
                             : "r"(addr));
            }
#pragma unroll
            for (int jj = 0; jj < 2; jj++) {
                uint32_t addr = bBase + swoff + jj * (16 * 128);
                asm volatile("ldmatrix.sync.aligned.m8n8.x4.shared.b16 {%0,%1,%2,%3}, [%4];\n"
                             : "=r"(bf[jj][0]), "=r"(bf[jj][1]), "=r"(bf[jj][2]), "=r"(bf[jj][3])
                             : "r"(addr));
            }
#pragma unroll
            for (int i = 0; i < 4; i++) {
#pragma unroll
                for (int j = 0; j < 4; j++) {
                    const int jj = j >> 1, s = j & 1;
                    asm volatile(
                        "mma.sync.aligned.m16n8k32.row.col.f16.e4m3.e4m3.f16 "
                        "{%0,%1}, {%2,%3,%4,%5}, {%6,%7}, {%0,%1};\n"
                        : "+r"(acc[i][j][0]), "+r"(acc[i][j][1])
                        : "r"(af[i][0]), "r"(af[i][1]), "r"(af[i][2]), "r"(af[i][3]),
                          "r"(bf[jj][s]), "r"(bf[jj][s + 2]));
                }
            }
        }
    }

    // ----- epilogue -----
#pragma unroll
    for (int i = 0; i < 4; i++) {
        int row0 = m0 + wm + i * 16 + (lane >> 2);
#pragma unroll
        for (int j = 0; j < 4; j++) {
            int col = n0 + wn + j * 8 + (lane & 3) * 2;
#pragma unroll
            for (int h = 0; h < 2; h++) {
                int r = row0 + h * 8;
                __half2 hv2 = *(__half2*)&acc[i][j][h];
                float v0 = __half2float(__low2half(hv2)) * desc;
                float v1 = __half2float(__high2half(hv2)) * desc;
                size_t off = (size_t)r * N + col;
                if (EPI == 0) {
                    *(float2*)((float*)Cv + off) = make_float2(v0, v1);
                } else if (EPI == 1) {
                    *(__nv_bfloat162*)((__nv_bfloat16*)Cv + off) =
                        __floats2bfloat162_rn(v0, v1);
                } else if (EPI == 2) {
                    uint16_t p = (uint16_t)f2e4m3(v0 * oscale) |
                                 ((uint16_t)f2e4m3(v1 * oscale) << 8);
                    *(uint16_t*)((uint8_t*)Cv + off) = p;
                } else if (EPI == 3) {
                    *(__nv_bfloat162*)((__nv_bfloat16*)Cv + off) =
                        __floats2bfloat162_rn(v0, v1);
                    uint16_t p = (uint16_t)f2e4m3(v0 * oscale) |
                                 ((uint16_t)f2e4m3(v1 * oscale) << 8);
                    *(uint16_t*)(out2 + (size_t)r * (2 * HH) + HH + col) = p;
                } else if (EPI == 4) {
                    float x0 = v0 + bias[col], x1 = v1 + bias[col + 1];
                    float g0 = 0.5f * x0 * (1.f + erff(x0 * 0.70710678118654752f));
                    float g1 = 0.5f * x1 * (1.f + erff(x1 * 0.70710678118654752f));
                    uint16_t p = (uint16_t)f2e4m3(g0 * oscale) |
                                 ((uint16_t)f2e4m3(g1 * oscale) << 8);
                    *(uint16_t*)((uint8_t*)Cv + off) = p;
                } else {
                    float x0 = v0 + bias[col], x1 = v1 + bias[col + 1];
                    float s0 = 1.f / (1.f + expf(-x0));
                    float s1 = 1.f / (1.f + expf(-x1));
                    __nv_bfloat162 cc = *(const __nv_bfloat162*)(crossp + off);
                    float2 hvv = *(const float2*)(hid + off);
                    *(float2*)((float*)Cv + off) =
                        make_float2(hvv.x + s0 * __bfloat162float(cc.x),
                                    hvv.y + s1 * __bfloat162float(cc.y));
                }
            }
        }
    }
}

// ---------------- host launcher ----------------
extern "C" void kernel_launch(void* const* d_in, const int* in_sizes, int n_in,
                              void* d_out, int out_size) {
    (void)in_sizes; (void)n_in; (void)out_size;
    const float* hidden = (const float*)d_in[0];
    const void*  amask  = d_in[1];
    const float* Wsim   = (const float*)d_in[2];
    const float* Wval   = (const float*)d_in[3];
    const float* Wg1    = (const float*)d_in[4];
    const float* bg1    = (const float*)d_in[5];
    const float* Wg2    = (const float*)d_in[6];
    const float* bg2    = (const float*)d_in[7];
    float* out = (float*)d_out;

    uint8_t *h8, *wsim8, *wval8, *wg18, *wg28, *normed8, *normedC8;
    uint8_t *vals8, *valsC8, *valsT8, *wts8, *gin8, *h18;
    __nv_bfloat16 *proj, *cross;
    float* sim;
    unsigned char* mask;
    int *cidx, *selfpos, *nvals;
    cudaGetSymbolAddress((void**)&h8,       g_hidden8);
    cudaGetSymbolAddress((void**)&wsim8,    g_Wsim8);
    cudaGetSymbolAddress((void**)&wval8,    g_Wval8);
    cudaGetSymbolAddress((void**)&wg18,     g_Wg18);
    cudaGetSymbolAddress((void**)&wg28,     g_Wg28);
    cudaGetSymbolAddress((void**)&proj,     g_proj_bf);
    cudaGetSymbolAddress((void**)&normed8,  g_normed8);
    cudaGetSymbolAddress((void**)&normedC8, g_normedC8);
    cudaGetSymbolAddress((void**)&vals8,    g_values8);
    cudaGetSymbolAddress((void**)&valsC8,   g_valuesC8);
    cudaGetSymbolAddress((void**)&valsT8,   g_valuesT8);
    cudaGetSymbolAddress((void**)&sim,      g_sim_f32);
    cudaGetSymbolAddress((void**)&wts8,     g_weights8);
    cudaGetSymbolAddress((void**)&cross,    g_cross_bf);
    cudaGetSymbolAddress((void**)&gin8,     g_gatein8);
    cudaGetSymbolAddress((void**)&h18,      g_h18);
    cudaGetSymbolAddress((void**)&mask,     g_mask_u8);
    cudaGetSymbolAddress((void**)&cidx,     g_cidx);
    cudaGetSymbolAddress((void**)&selfpos,  g_selfpos);
    cudaGetSymbolAddress((void**)&nvals,    g_nvals);

    cudaFuncSetAttribute(gemm_nt_fp8<0>, cudaFuncAttributeMaxDynamicSharedMemorySize, GEMM_DYN_SMEM);
    cudaFuncSetAttribute(gemm_nt_fp8<1>, cudaFuncAttributeMaxDynamicSharedMemorySize, GEMM_DYN_SMEM);
    cudaFuncSetAttribute(gemm_nt_fp8<2>, cudaFuncAttributeMaxDynamicSharedMemorySize, GEMM_DYN_SMEM);
    cudaFuncSetAttribute(gemm_nt_fp8<3>, cudaFuncAttributeMaxDynamicSharedMemorySize, GEMM_DYN_SMEM);
    cudaFuncSetAttribute(gemm_nt_fp8<4>, cudaFuncAttributeMaxDynamicSharedMemorySize, GEMM_DYN_SMEM);
    cudaFuncSetAttribute(gemm_nt_fp8<5>, cudaFuncAttributeMaxDynamicSharedMemorySize, GEMM_DYN_SMEM);

    // 0: mask detect + expand + compaction (cidx/selfpos/nv/nvp)
    mask_compact_kernel<<<1, 256>>>((const unsigned char*)amask, mask, cidx, selfpos, nvals);
    // 1: hidden -> fp8 (x16) + gatein first half
    hidden_to_fp8_kernel<<<(unsigned)(((long)BB * HH / 4 + 255) / 256), 256>>>(hidden, h8, gin8);
    // 2: Wsim -> fp8 (x256)
    {
        long n4 = (long)HH * HH / 4;
        f32_to_fp8_kernel<<<(unsigned)((n4 + 255) / 256), 256>>>(Wsim, wsim8, 256.f, n4);
    }
    // 3: proj = hidden @ Wsim^T -> bf16   (desc 1/(16*256))
    gemm_nt_fp8<1><<<dim3(HH / 128, BB / 128), 256, GEMM_DYN_SMEM>>>(
        h8, wsim8, proj, BB, HH, HH, HH, HH, 1.f / 4096.f, 0.f,
        nullptr, nullptr, nullptr, nullptr, nullptr, nullptr);
    // 4: normalize -> normed fp8 (x64)
    normalize_rows_kernel<<<BB, 256>>>(proj, normed8);
    // 5: gather compacted normed rows (valid columns of sim)
    gather_rows_kernel<<<BB, 128>>>(normed8, normedC8, cidx, nvals, HH);
    // 6: sim = normed @ normedC^T -> f32 [B, nvp] (stride BB), desc 1/(64*64)
    gemm_nt_fp8<0><<<dim3(BB / 128, BB / 128), 256, GEMM_DYN_SMEM>>>(
        normed8, normedC8, sim, BB, BB, HH, HH, HH, 1.f / 4096.f, 0.f,
        nullptr, nullptr, nullptr, nullptr, nullptr, nvals);
    // 7: Wval -> fp8 (x256)
    {
        long n4 = (long)HH * HH / 4;
        f32_to_fp8_kernel<<<(unsigned)((n4 + 255) / 256), 256>>>(Wval, wval8, 256.f, n4);
    }
    // 8: softmax over compacted columns -> weights fp8 (x16384), zero-padded
    softmax_mask_kernel<<<BB, 256>>>(sim, selfpos, nvals, wts8);
    // 9: values = hidden @ Wval^T -> fp8 (x16)
    gemm_nt_fp8<2><<<dim3(HH / 128, BB / 128), 256, GEMM_DYN_SMEM>>>(
        h8, wval8, vals8, BB, HH, HH, HH, HH, 1.f / 4096.f, 16.f,
        nullptr, nullptr, nullptr, nullptr, nullptr, nullptr);
    // 10: gather compacted values rows
    gather_rows_kernel<<<BB, 128>>>(vals8, valsC8, cidx, nvals, HH);
    // 11: transpose valuesC -> valuesT [HH, BB stride]
    transpose_u8_kernel<<<dim3(HH / 32, BB / 32), dim3(32, 8)>>>(valsC8, valsT8, BB, HH);
    // 12: cross = weightsC @ valuesC (dynamic K = nvp) -> bf16 + fp8 gatein
    //     desc = 1/(16384*16)
    gemm_nt_fp8<3><<<dim3(HH / 128, BB / 128), 256, GEMM_DYN_SMEM>>>(
        wts8, valsT8, cross, BB, HH, BB, BB, BB, 1.f / 262144.f, 16.f,
        nullptr, nullptr, nullptr, gin8, nvals, nullptr);
    // 13: Wg1 -> fp8 (x256)
    {
        long n4 = (long)GHH * 2 * HH / 4;
        f32_to_fp8_kernel<<<(unsigned)((n4 + 255) / 256), 256>>>(Wg1, wg18, 256.f, n4);
    }
    // 14: h1 = gelu(gatein @ Wg1^T + b1) -> fp8 (x64)   (desc 1/(16*256))
    gemm_nt_fp8<4><<<dim3(GHH / 128, BB / 128), 256, GEMM_DYN_SMEM>>>(
        gin8, wg18, h18, BB, GHH, 2 * HH, 2 * HH, 2 * HH, 1.f / 4096.f, 64.f,
        bg1, nullptr, nullptr, nullptr, nullptr, nullptr);
    // 15: Wg2 -> fp8 (x256)
    {
        long n4 = (long)HH * GHH / 4;
        f32_to_fp8_kernel<<<(unsigned)((n4 + 255) / 256), 256>>>(Wg2, wg28, 256.f, n4);
    }
    // 16: out = hidden + sigmoid(h1 @ Wg2^T + b2) * cross   (desc 1/(64*256))
    gemm_nt_fp8<5><<<dim3(HH / 128, BB / 128), 256, GEMM_DYN_SMEM>>>(
        h18, wg28, out, BB, HH, GHH, GHH, GHH, 1.f / 16384.f, 0.f,
        bg2, hidden, cross, nullptr, nullptr, nullptr);
}

// round 16
// speedup vs baseline: 1.3237x; 1.0854x over previous
#include <cuda_runtime.h>
#include <cuda_bf16.h>
#include <cuda_fp16.h>
#include <cuda_fp8.h>
#include <cstdint>
#include <math.h>

#define BB 8192
#define HH 4096
#define GHH 1024

// ---------------- scratch (device globals; allocation-free rule) ----------------
__device__ uint8_t       g_hidden8[(size_t)BB * HH];
__device__ uint8_t       g_hiddenC8[(size_t)BB * HH];   // compacted valid rows of hidden
__device__ uint8_t       g_Wsim8[(size_t)HH * HH];
__device__ uint8_t       g_Wval8[(size_t)HH * HH];
__device__ uint8_t       g_Wg18[(size_t)GHH * 2 * HH];
__device__ uint8_t       g_Wg28[(size_t)HH * GHH];
__device__ __nv_bfloat16 g_proj_bf[(size_t)BB * HH];
__device__ uint8_t       g_normed8[(size_t)BB * HH];
__device__ uint8_t       g_normedC8[(size_t)BB * HH];   // compacted valid rows
__device__ uint8_t       g_valuesC8[(size_t)BB * HH];   // values of valid rows (padded)
__device__ uint8_t       g_valuesT8[(size_t)HH * BB];   // transpose of compacted
__device__ float         g_sim_f32[(size_t)BB * BB];
__device__ uint8_t       g_weights8[(size_t)BB * BB];   // compacted cols, stride BB
__device__ __nv_bfloat16 g_cross_bf[(size_t)BB * HH];
__device__ uint8_t       g_gatein8[(size_t)BB * 2 * HH];
__device__ uint8_t       g_h18[(size_t)BB * GHH];
__device__ unsigned char g_mask_u8[BB];
__device__ int           g_cidx[BB];
__device__ int           g_selfpos[BB];
__device__ int           g_nvals[2];                    // [0]=nv, [1]=nvp (pad 128)

// scales: hidden x16, W x256, normed x64, weights x16384, values x16, cross x16, h1 x64

// ---------------- helpers ----------------
__device__ __forceinline__ uint32_t smem_u32(const void* p) {
    return (uint32_t)__cvta_generic_to_shared(p);
}
__device__ __forceinline__ uint8_t f2e4m3(float v) {
    return (uint8_t)__nv_cvt_float_to_fp8(v, __NV_SATFINITE, __NV_E4M3);
}

// ---------------- mask detect + expand + compact (single block) --------------
__global__ void mask_compact_kernel(const unsigned char* m, unsigned char* out,
                                    int* cidx, int* selfpos, int* nvals) {
    __shared__ int s_nonbin, s_off4, s_fbad, s_bfbad, s_code;
    __shared__ int cnt[257];
    const int t = threadIdx.x;
    if (t == 0) { s_nonbin = 0; s_off4 = 0; s_fbad = 0; s_bfbad = 0; }
    __syncthreads();
    int nonbin = 0, off4 = 0, fbad = 0, bfbad = 0;
    for (int j = t; j < 8192; j += 256) {
        unsigned char b = m[j];
        if (b > 1) nonbin++;
        if ((j & 3) != 0 && b != 0) off4++;
    }
    const uint32_t* u = (const uint32_t*)m;
    for (int i = t; i < 2048; i += 256) {
        uint32_t w = u[i];
        if (!(w == 0u || w == 0x3f800000u)) fbad++;
    }
    const uint16_t* h = (const uint16_t*)m;
    for (int i = t; i < 4096; i += 256) {
        uint16_t x = h[i];
        if (!(x == 0 || x == 0x3f80)) bfbad++;
    }
    atomicAdd(&s_nonbin, nonbin);
    atomicAdd(&s_off4, off4);
    atomicAdd(&s_fbad, fbad);
    atomicAdd(&s_bfbad, bfbad);
    __syncthreads();
    if (t == 0) {
        int code;
        if (s_nonbin == 0) code = (s_off4 > 0) ? 0 : 1;
        else if (s_fbad == 0) code = 2;
        else if (s_bfbad == 0) code = 3;
        else code = 1;
        s_code = code;
    }
    __syncthreads();
    const int code = s_code;

    bool vloc[32];
    int c = 0;
#pragma unroll
    for (int e = 0; e < 32; e++) {
        int i = t * 32 + e;
        bool v;
        if (code == 0)      v = ((const unsigned char*)m)[i] != 0;
        else if (code == 1) v = ((const int*)m)[i] != 0;
        else if (code == 2) v = ((const float*)m)[i] != 0.0f;
        else                v = (((const uint16_t*)m)[i] & 0x7fff) != 0;
        vloc[e] = v;
        out[i] = v ? 1 : 0;
        c += v ? 1 : 0;
    }
    cnt[t] = c;
    __syncthreads();
    if (t == 0) {
        int run = 0;
        for (int i = 0; i < 256; i++) { int x = cnt[i]; cnt[i] = run; run += x; }
        cnt[256] = run;
        nvals[0] = run;
        nvals[1] = (run + 127) & ~127;
    }
    __syncthreads();
    int pos = cnt[t];
#pragma unroll
    for (int e = 0; e < 32; e++) {
        int i = t * 32 + e;
        if (vloc[e]) { cidx[pos] = i; selfpos[i] = pos; pos++; }
        else selfpos[i] = -1;
    }
}

// ---------------- row gather (compaction): dst[r] = src[cidx[r]], zero pad ----
__global__ void gather_rows_kernel(const uint8_t* __restrict__ src,
                                   uint8_t* __restrict__ dst,
                                   const int* __restrict__ cidx,
                                   const int* __restrict__ nvals, int C) {
    int row = blockIdx.x;
    int nv = nvals[0], nvp = nvals[1];
    if (row >= nvp) return;
    uint4* d = (uint4*)(dst + (size_t)row * C);
    if (row < nv) {
        const uint4* s = (const uint4*)(src + (size_t)cidx[row] * C);
        for (int j = threadIdx.x; j < C / 16; j += blockDim.x) d[j] = s[j];
    } else {
        uint4 z = make_uint4(0, 0, 0, 0);
        for (int j = threadIdx.x; j < C / 16; j += blockDim.x) d[j] = z;
    }
}

// ---------------- fp32 -> fp8 convert (scale) ----------------
__global__ void f32_to_fp8_kernel(const float* __restrict__ in,
                                  uint8_t* __restrict__ out, float scale, long n4) {
    long i = (long)blockIdx.x * blockDim.x + threadIdx.x;
    if (i < n4) {
        float4 v = ((const float4*)in)[i];
        uint32_t p = (uint32_t)f2e4m3(v.x * scale) |
                     ((uint32_t)f2e4m3(v.y * scale) << 8) |
                     ((uint32_t)f2e4m3(v.z * scale) << 16) |
                     ((uint32_t)f2e4m3(v.w * scale) << 24);
        ((uint32_t*)out)[i] = p;
    }
}

// hidden -> g_hidden8 AND first half of g_gatein8, scale 16
__global__ void hidden_to_fp8_kernel(const float* __restrict__ in,
                                     uint8_t* __restrict__ out,
                                     uint8_t* __restrict__ gatein) {
    long i = ((long)blockIdx.x * blockDim.x + threadIdx.x);
    if (i >= (long)BB * HH / 4) return;
    float4 v = ((const float4*)in)[i];
    uint32_t p = (uint32_t)f2e4m3(v.x * 16.f) |
                 ((uint32_t)f2e4m3(v.y * 16.f) << 8) |
                 ((uint32_t)f2e4m3(v.z * 16.f) << 16) |
                 ((uint32_t)f2e4m3(v.w * 16.f) << 24);
    ((uint32_t*)out)[i] = p;
    long e = i * 4;
    long b = e >> 12;
    int  j = (int)(e & (HH - 1));
    *(uint32_t*)(gatein + b * (2 * HH) + j) = p;
}

// ---------------- row L2 normalize: bf16 proj -> fp8 normed (x64) ----------------
__global__ void normalize_rows_kernel(const __nv_bfloat16* __restrict__ p,
                                      uint8_t* __restrict__ normed) {
    int row = blockIdx.x;
    const __nv_bfloat16* r = p + (size_t)row * HH;
    float s = 0.f;
    for (int j = threadIdx.x; j < HH; j += 256) {
        float v = __bfloat162float(r[j]);
        s += v * v;
    }
#pragma unroll
    for (int o = 16; o > 0; o >>= 1) s += __shfl_xor_sync(0xffffffffu, s, o);
    __shared__ float ws[8];
    int w = threadIdx.x >> 5, l = threadIdx.x & 31;
    if (l == 0) ws[w] = s;
    __syncthreads();
    if (threadIdx.x < 32) {
        float x = (threadIdx.x < 8) ? ws[threadIdx.x] : 0.f;
#pragma unroll
        for (int o = 4; o > 0; o >>= 1) x += __shfl_xor_sync(0xffffffffu, x, o);
        if (threadIdx.x == 0) ws[0] = x;
    }
    __syncthreads();
    float scale = 64.f / fmaxf(sqrtf(ws[0]), 1e-12f);
    uint8_t* nr = normed + (size_t)row * HH;
    for (int j = threadIdx.x; j < HH / 4; j += 256) {
        float v0 = __bfloat162float(r[j * 4 + 0]) * scale;
        float v1 = __bfloat162float(r[j * 4 + 1]) * scale;
        float v2 = __bfloat162float(r[j * 4 + 2]) * scale;
        float v3 = __bfloat162float(r[j * 4 + 3]) * scale;
        ((uint32_t*)nr)[j] = (uint32_t)f2e4m3(v0) | ((uint32_t)f2e4m3(v1) << 8) |
                             ((uint32_t)f2e4m3(v2) << 16) | ((uint32_t)f2e4m3(v3) << 24);
    }
}

// ------- masked softmax over compacted sim: f32 -> fp8 weights (x16384) -------
__global__ void softmax_mask_kernel(const float* __restrict__ sim,
                                    const int* __restrict__ selfpos,
                                    const int* __restrict__ nvals,
                                    uint8_t* __restrict__ wts) {
    int row = blockIdx.x;
    int nv = nvals[0], nvp = nvals[1];
    int sp = selfpos[row];
    __shared__ float sv[BB];
    __shared__ float red[8];
    const float* sr = sim + (size_t)row * BB;
    float mx = -INFINITY;
    for (int j = threadIdx.x; j < nv; j += 256) {
        float v = (j == sp) ? -INFINITY : sr[j];
        sv[j] = v;
        mx = fmaxf(mx, v);
    }
#pragma unroll
    for (int o = 16; o > 0; o >>= 1) mx = fmaxf(mx, __shfl_xor_sync(0xffffffffu, mx, o));
    int w = threadIdx.x >> 5, l = threadIdx.x & 31;
    if (l == 0) red[w] = mx;
    __syncthreads();
    if (threadIdx.x < 32) {
        float x = (threadIdx.x < 8) ? red[threadIdx.x] : -INFINITY;
#pragma unroll
        for (int o = 4; o > 0; o >>= 1) x = fmaxf(x, __shfl_xor_sync(0xffffffffu, x, o));
        if (threadIdx.x == 0) red[0] = x;
    }
    __syncthreads();
    float M = red[0];
    __syncthreads();
    float sum = 0.f;
    for (int j = threadIdx.x; j < nv; j += 256) {
        float v = sv[j];
        float e = (v == -INFINITY) ? 0.f : __expf(v - M);
        sv[j] = e;
        sum += e;
    }
#pragma unroll
    for (int o = 16; o > 0; o >>= 1) sum += __shfl_xor_sync(0xffffffffu, sum, o);
    if (l == 0) red[w] = sum;
    __syncthreads();
    if (threadIdx.x < 32) {
        float x = (threadIdx.x < 8) ? red[threadIdx.x] : 0.f;
#pragma unroll
        for (int o = 4; o > 0; o >>= 1) x += __shfl_xor_sync(0xffffffffu, x, o);
        if (threadIdx.x == 0) red[0] = x;
    }
    __syncthreads();
    float S = red[0];
    float inv = (S > 0.f) ? 16384.f / S : 0.f;
    uint8_t* wr = wts + (size_t)row * BB;
    for (int j = threadIdx.x; j < nvp; j += 256)
        wr[j] = (j < nv) ? f2e4m3(sv[j] * inv) : (uint8_t)0;
}

// ---------------- u8 transpose (valuesC -> valuesT) ----------------
__global__ void transpose_u8_kernel(const uint8_t* __restrict__ in,
                                    uint8_t* __restrict__ out, int R, int C) {
    __shared__ uint8_t tile[32][33];
    int x = blockIdx.x * 32 + threadIdx.x;
    int y0 = blockIdx.y * 32 + threadIdx.y;
#pragma unroll
    for (int i = 0; i < 32; i += 8)
        tile[threadIdx.y + i][threadIdx.x] = in[(size_t)(y0 + i) * C + x];
    __syncthreads();
    int x2 = blockIdx.y * 32 + threadIdx.x;
    int y2 = blockIdx.x * 32 + threadIdx.y;
#pragma unroll
    for (int i = 0; i < 32; i += 8)
        out[(size_t)(y2 + i) * R + x2] = tile[threadIdx.x][threadIdx.y + i];
}

// ================= fp8 NT GEMM (mma.sync m16n8k32 e4m3, f16 accum) ==========
// C[M,N] = A[M,K] * B[N,K]^T, lda/ldb row strides (bytes).
// dynk:   if non-null, effective K = dynk[1] (nvp, mult of 128).
// dyncol: if non-null, CTAs with n0 >= dyncol[1] exit (compacted N).
// dynrow: if non-null, CTAs with m0 >= dynrow[1] exit (compacted M).
// CTA 128x128, warp 64x32, 2-stage cp.async, XOR swizzle, 3 CTAs/SM, f16 acc.
// EPI: 0=f32(desc), 1=bf16(desc), 2=fp8(desc*oscale),
//      3=cross: bf16 + fp8 into gatein second half,
//      4=gelu(desc*acc+bias)->fp8, 5=hid+sigmoid(desc*acc+bias)*cross->f32
#define A_BYTES (128 * 128)
#define B_BYTES (128 * 128)
#define STAGE_BYTES (A_BYTES + B_BYTES)
#define GEMM_DYN_SMEM (2 * STAGE_BYTES + 256)

template <int EPI>
__global__ void __launch_bounds__(256, 3)
gemm_nt_fp8(const uint8_t* __restrict__ A,
            const uint8_t* __restrict__ Bm,
            void* __restrict__ Cv,
            int M, int N, int K, int lda, int ldb,
            float desc, float oscale,
            const float* __restrict__ bias,
            const float* __restrict__ hid,
            const __nv_bfloat16* __restrict__ crossp,
            uint8_t* __restrict__ out2,
            const int* __restrict__ dynk,
            const int* __restrict__ dyncol,
            const int* __restrict__ dynrow) {
    const int n0 = blockIdx.x * 128;
    const int m0 = blockIdx.y * 128;
    if (dyncol && n0 >= dyncol[1]) return;
    if (dynrow && m0 >= dynrow[1]) return;
    const int Keff = dynk ? dynk[1] : K;
    const int KT = Keff >> 7;

    extern __shared__ char dynsm[];
    const uint32_t sbase = (smem_u32(dynsm) + 127u) & ~127u;

    const int t = threadIdx.x;
    const int warp = t >> 5, lane = t & 31;
    const int wm = (warp & 1) * 64;
    const int wn = (warp >> 1) * 32;

    // ---- producer addressing (XOR swizzle on 16B chunks) ----
    const int frow = t >> 3;
    const int fch = t & 7;
    const uint32_t swch = (uint32_t)(fch ^ (frow & 7)) * 16;
    const uint32_t sAoff = (uint32_t)frow * 128 + swch;
    const uint32_t sBoff = A_BYTES + (uint32_t)frow * 128 + swch;
    const uint8_t* gA = A + (size_t)(m0 + frow) * lda + fch * 16;
    const uint8_t* gB = Bm + (size_t)(n0 + frow) * ldb + fch * 16;

    // ---- consumer addressing ----
    const int crow = lane & 15;
    const int hi = lane >> 4;
    const int rx = crow & 7;
    const uint32_t aRow0 = (uint32_t)(wm + crow) * 128;
    const uint32_t bRow0 = A_BYTES + (uint32_t)(wn + crow) * 128;

    uint32_t acc[4][4][2];
#pragma unroll
    for (int i = 0; i < 4; i++)
#pragma unroll
        for (int j = 0; j < 4; j++) { acc[i][j][0] = 0u; acc[i][j][1] = 0u; }

    auto fill = [&](int kt, int st) {
        const uint32_t stb = sbase + st * STAGE_BYTES;
        const size_t kb = (size_t)kt * 128;
#pragma unroll
        for (int i = 0; i < 4; i++) {
            uint32_t dst = stb + sAoff + i * (32 * 128);
            const void* gp = gA + kb + (size_t)i * 32 * lda;
            asm volatile("cp.async.cg.shared.global [%0], [%1], 16;\n" ::"r"(dst), "l"(gp));
        }
#pragma unroll
        for (int i = 0; i < 4; i++) {
            uint32_t dst = stb + sBoff + i * (32 * 128);
            const void* gp = gB + kb + (size_t)i * 32 * ldb;
            asm volatile("cp.async.cg.shared.global [%0], [%1], 16;\n" ::"r"(dst), "l"(gp));
        }
    };

    if (KT > 0) {
        fill(0, 0);
        asm volatile("cp.async.commit_group;\n" ::);
    }

    for (int kt = 0; kt < KT; ++kt) {
        asm volatile("cp.async.wait_group 0;\n" ::);
        __syncthreads();
        if (kt + 1 < KT) fill(kt + 1, (kt + 1) & 1);
        asm volatile("cp.async.commit_group;\n" ::);

        const uint32_t stb = sbase + (kt & 1) * STAGE_BYTES;
        const uint32_t aBase = stb + aRow0;
        const uint32_t bBase = stb + bRow0;
#pragma unroll
        for (int ks = 0; ks < 4; ++ks) {
            const uint32_t swoff = (uint32_t)(((2 * ks + hi) ^ rx) << 4);
            uint32_t af[4][4], bf[2][4];
#pragma unroll
            for (int i = 0; i < 4; i++) {
                uint32_t addr = aBase + swoff + i * (16 * 128);
                asm volatile("ldmatrix.sync.aligned.m8n8.x4.shared.b16 {%0,%1,%2,%3}, [%4];\n"
                             : "=r"(af[i][0]), "=r"(af[i][1]), "=r"(af[i][2]), "=r"(af[i][3])
                             : "r"(addr));
            }
#pragma unroll
            for (int jj = 0; jj < 2; jj++) {
                uint32_t addr = bBase + swoff + jj * (16 * 128);
                asm volatile("ldmatrix.sync.aligned.m8n8.x4.shared.b16 {%0,%1,%2,%3}, [%4];\n"
                             : "=r"(bf[jj][0]), "=r"(bf[jj][1]), "=r"(bf[jj][2]), "=r"(bf[jj][3])
                             : "r"(addr));
            }
#pragma unroll
            for (int i = 0; i < 4; i++) {
#pragma unroll
                for (int j = 0; j < 4; j++) {
                    const int jj = j >> 1, s = j & 1;
                    asm volatile(
                        "mma.sync.aligned.m16n8k32.row.col.f16.e4m3.e4m3.f16 "
                        "{%0,%1}, {%2,%3,%4,%5}, {%6,%7}, {%0,%1};\n"
                        : "+r"(acc[i][j][0]), "+r"(acc[i][j][1])
                        : "r"(af[i][0]), "r"(af[i][1]), "r"(af[i][2]), "r"(af[i][3]),
                          "r"(bf[jj][s]), "r"(bf[jj][s + 2]));
                }
            }
        }
    }

    // ----- epilogue -----
#pragma unroll
    for (int i = 0; i < 4; i++) {
        int row0 = m0 + wm + i * 16 + (lane >> 2);
#pragma unroll
        for (int j = 0; j < 4; j++) {
            int col = n0 + wn + j * 8 + (lane & 3) * 2;
#pragma unroll
            for (int h = 0; h < 2; h++) {
                int r = row0 + h * 8;
                __half2 hv2 = *(__half2*)&acc[i][j][h];
                float v0 = __half2float(__low2half(hv2)) * desc;
                float v1 = __half2float(__high2half(hv2)) * desc;
                size_t off = (size_t)r * N + col;
                if (EPI == 0) {
                    *(float2*)((float*)Cv + off) = make_float2(v0, v1);
                } else if (EPI == 1) {
                    *(__nv_bfloat162*)((__nv_bfloat16*)Cv + off) =
                        __floats2bfloat162_rn(v0, v1);
                } else if (EPI == 2) {
                    uint16_t p = (uint16_t)f2e4m3(v0 * oscale) |
                                 ((uint16_t)f2e4m3(v1 * oscale) << 8);
                    *(uint16_t*)((uint8_t*)Cv + off) = p;
                } else if (EPI == 3) {
                    *(__nv_bfloat162*)((__nv_bfloat16*)Cv + off) =
                        __floats2bfloat162_rn(v0, v1);
                    uint16_t p = (uint16_t)f2e4m3(v0 * oscale) |
                                 ((uint16_t)f2e4m3(v1 * oscale) << 8);
                    *(uint16_t*)(out2 + (size_t)r * (2 * HH) + HH + col) = p;
                } else if (EPI == 4) {
                    float x0 = v0 + bias[col], x1 = v1 + bias[col + 1];
                    float g0 = 0.5f * x0 * (1.f + erff(x0 * 0.70710678118654752f));
                    float g1 = 0.5f * x1 * (1.f + erff(x1 * 0.70710678118654752f));
                    uint16_t p = (uint16_t)f2e4m3(g0 * oscale) |
                                 ((uint16_t)f2e4m3(g1 * oscale) << 8);
                    *(uint16_t*)((uint8_t*)Cv + off) = p;
                } else {
                    float x0 = v0 + bias[col], x1 = v1 + bias[col + 1];
                    float s0 = 1.f / (1.f + expf(-x0));
                    float s1 = 1.f / (1.f + expf(-x1));
                    __nv_bfloat162 cc = *(const __nv_bfloat162*)(crossp + off);
                    float2 hvv = *(const float2*)(hid + off);
                    *(float2*)((float*)Cv + off) =
                        make_float2(hvv.x + s0 * __bfloat162float(cc.x),
                                    hvv.y + s1 * __bfloat162float(cc.y));
                }
            }
        }
    }
}

// ---------------- host launcher ----------------
extern "C" void kernel_launch(void* const* d_in, const int* in_sizes, int n_in,
                              void* d_out, int out_size) {
    (void)in_sizes; (void)n_in; (void)out_size;
    const float* hidden = (const float*)d_in[0];
    const void*  amask  = d_in[1];
    const float* Wsim   = (const float*)d_in[2];
    const float* Wval   = (const float*)d_in[3];
    const float* Wg1    = (const float*)d_in[4];
    const float* bg1    = (const float*)d_in[5];
    const float* Wg2    = (const float*)d_in[6];
    const float* bg2    = (const float*)d_in[7];
    float* out = (float*)d_out;

    uint8_t *h8, *hC8, *wsim8, *wval8, *wg18, *wg28, *normed8, *normedC8;
    uint8_t *valsC8, *valsT8, *wts8, *gin8, *h18;
    __nv_bfloat16 *proj, *cross;
    float* sim;
    unsigned char* mask;
    int *cidx, *selfpos, *nvals;
    cudaGetSymbolAddress((void**)&h8,       g_hidden8);
    cudaGetSymbolAddress((void**)&hC8,      g_hiddenC8);
    cudaGetSymbolAddress((void**)&wsim8,    g_Wsim8);
    cudaGetSymbolAddress((void**)&wval8,    g_Wval8);
    cudaGetSymbolAddress((void**)&wg18,     g_Wg18);
    cudaGetSymbolAddress((void**)&wg28,     g_Wg28);
    cudaGetSymbolAddress((void**)&proj,     g_proj_bf);
    cudaGetSymbolAddress((void**)&normed8,  g_normed8);
    cudaGetSymbolAddress((void**)&normedC8, g_normedC8);
    cudaGetSymbolAddress((void**)&valsC8,   g_valuesC8);
    cudaGetSymbolAddress((void**)&valsT8,   g_valuesT8);
    cudaGetSymbolAddress((void**)&sim,      g_sim_f32);
    cudaGetSymbolAddress((void**)&wts8,     g_weights8);
    cudaGetSymbolAddress((void**)&cross,    g_cross_bf);
    cudaGetSymbolAddress((void**)&gin8,     g_gatein8);
    cudaGetSymbolAddress((void**)&h18,      g_h18);
    cudaGetSymbolAddress((void**)&mask,     g_mask_u8);
    cudaGetSymbolAddress((void**)&cidx,     g_cidx);
    cudaGetSymbolAddress((void**)&selfpos,  g_selfpos);
    cudaGetSymbolAddress((void**)&nvals,    g_nvals);

    cudaFuncSetAttribute(gemm_nt_fp8<0>, cudaFuncAttributeMaxDynamicSharedMemorySize, GEMM_DYN_SMEM);
    cudaFuncSetAttribute(gemm_nt_fp8<1>, cudaFuncAttributeMaxDynamicSharedMemorySize, GEMM_DYN_SMEM);
    cudaFuncSetAttribute(gemm_nt_fp8<2>, cudaFuncAttributeMaxDynamicSharedMemorySize, GEMM_DYN_SMEM);
    cudaFuncSetAttribute(gemm_nt_fp8<3>, cudaFuncAttributeMaxDynamicSharedMemorySize, GEMM_DYN_SMEM);
    cudaFuncSetAttribute(gemm_nt_fp8<4>, cudaFuncAttributeMaxDynamicSharedMemorySize, GEMM_DYN_SMEM);
    cudaFuncSetAttribute(gemm_nt_fp8<5>, cudaFuncAttributeMaxDynamicSharedMemorySize, GEMM_DYN_SMEM);

    // 0: mask detect + expand + compaction (cidx/selfpos/nv/nvp)
    mask_compact_kernel<<<1, 256>>>((const unsigned char*)amask, mask, cidx, selfpos, nvals);
    // 1: hidden -> fp8 (x16) + gatein first half
    hidden_to_fp8_kernel<<<(unsigned)(((long)BB * HH / 4 + 255) / 256), 256>>>(hidden, h8, gin8);
    // 2: gather compacted hidden rows (for values GEMM with M = nvp)
    gather_rows_kernel<<<BB, 128>>>(h8, hC8, cidx, nvals, HH);
    // 3: Wsim -> fp8 (x256)
    {
        long n4 = (long)HH * HH / 4;
        f32_to_fp8_kernel<<<(unsigned)((n4 + 255) / 256), 256>>>(Wsim, wsim8, 256.f, n4);
    }
    // 4: proj = hidden @ Wsim^T -> bf16   (desc 1/(16*256))
    gemm_nt_fp8<1><<<dim3(HH / 128, BB / 128), 256, GEMM_DYN_SMEM>>>(
        h8, wsim8, proj, BB, HH, HH, HH, HH, 1.f / 4096.f, 0.f,
        nullptr, nullptr, nullptr, nullptr, nullptr, nullptr, nullptr);
    // 5: normalize -> normed fp8 (x64)
    normalize_rows_kernel<<<BB, 256>>>(proj, normed8);
    // 6: gather compacted normed rows (valid columns of sim)
    gather_rows_kernel<<<BB, 128>>>(normed8, normedC8, cidx, nvals, HH);
    // 7: sim = normed @ normedC^T -> f32 [B, nvp] (stride BB), desc 1/(64*64)
    gemm_nt_fp8<0><<<dim3(BB / 128, BB / 128), 256, GEMM_DYN_SMEM>>>(
        normed8, normedC8, sim, BB, BB, HH, HH, HH, 1.f / 4096.f, 0.f,
        nullptr, nullptr, nullptr, nullptr, nullptr, nvals, nullptr);
    // 8: Wval -> fp8 (x256)
    {
        long n4 = (long)HH * HH / 4;
        f32_to_fp8_kernel<<<(unsigned)((n4 + 255) / 256), 256>>>(Wval, wval8, 256.f, n4);
    }
    // 9: softmax over compacted columns -> weights fp8 (x16384), zero-padded
    softmax_mask_kernel<<<BB, 256>>>(sim, selfpos, nvals, wts8);
    // 10: valuesC = hiddenC @ Wval^T -> fp8 (x16), dynamic M = nvp
    gemm_nt_fp8<2><<<dim3(HH / 128, BB / 128), 256, GEMM_DYN_SMEM>>>(
        hC8, wval8, valsC8, BB, HH, HH, HH, HH, 1.f / 4096.f, 16.f,
        nullptr, nullptr, nullptr, nullptr, nullptr, nullptr, nvals);
    // 11: transpose valuesC -> valuesT [HH, BB stride]
    transpose_u8_kernel<<<dim3(HH / 32, BB / 32), dim3(32, 8)>>>(valsC8, valsT8, BB, HH);
    // 12: cross = weightsC @ valuesC (dynamic K = nvp) -> bf16 + fp8 gatein
    //     desc = 1/(16384*16)
    gemm_nt_fp8<3><<<dim3(HH / 128, BB / 128), 256, GEMM_DYN_SMEM>>>(
        wts8, valsT8, cross, BB, HH, BB, BB, BB, 1.f / 262144.f, 16.f,
        nullptr, nullptr, nullptr, gin8, nvals, nullptr, nullptr);
    // 13: Wg1 -> fp8 (x256)
    {
        long n4 = (long)GHH * 2 * HH / 4;
        f32_to_fp8_kernel<<<(unsigned)((n4 + 255) / 256), 256>>>(Wg1, wg18, 256.f, n4);
    }
    // 14: h1 = gelu(gatein @ Wg1^T + b1) -> fp8 (x64)   (desc 1/(16*256))
    gemm_nt_fp8<4><<<dim3(GHH / 128, BB / 128), 256, GEMM_DYN_SMEM>>>(
        gin8, wg18, h18, BB, GHH, 2 * HH, 2 * HH, 2 * HH, 1.f / 4096.f, 64.f,
        bg1, nullptr, nullptr, nullptr, nullptr, nullptr, nullptr);
    // 15: Wg2 -> fp8 (x256)
    {
        long n4 = (long)HH * GHH / 4;
        f32_to_fp8_kernel<<<(unsigned)((n4 + 255) / 256), 256>>>(Wg2, wg28, 256.f, n4);
    }
    // 16: out = hidden + sigmoid(h1 @ Wg2^T + b2) * cross   (desc 1/(64*256))
    gemm_nt_fp8<5><<<dim3(HH / 128, BB / 128), 256, GEMM_DYN_SMEM>>>(
        h18, wg28, out, BB, HH, GHH, GHH, GHH, 1.f / 16384.f, 0.f,
        bg2, hidden, cross, nullptr, nullptr, nullptr, nullptr);
}